// round 13
// baseline (speedup 1.0000x reference)
#include <cuda_runtime.h>
#include <cuda_bf16.h>
#include <mma.h>

// Net_12403865551680 — 2-layer GCN + mean-pool + Kronecker BN-MLP head.
// R10: 246.9 (best; gp = 40-node/1000-thr/x2, MLP capped by 65-reg ceiling).
// R11 (+43): x4 unroll spilled at 1000 thr. R12 (+13): warp-per-node lost to
//      csr pointer-chase serialization + idle lanes.
// R13: gp at 800 thr (32 nodes x 25) -> 81-reg ceiling fits x4 unroll (MLP 4);
//      hp2 stored bf16 (halves gather2 traffic). Rest = R10 config.

using namespace nvcuda;

typedef unsigned long long ull;

#define NN 100000
#define NE 1600000
#define NG 1024

struct __align__(8) bf4 { __nv_bfloat162 a, b; };

// ---------------- scratch (zero-initialized at module load) ----------------
__device__ __align__(128) bf4   d_hp1b[NN * 25];    // feat@W1, bf16, 100 dims/node
__device__ __align__(128) __nv_bfloat162 d_hp2b[NN * 10];  // h1@W2, bf16, 20 dims/node
__device__ int   d_deg[NN];                         // zeroed by scanC each run
__device__ int   d_bsum[98];
__device__ int   d_rowstart[NN + 1];
__device__ int   d_cursor[NN];
__device__ int   d_csr[NE];
__device__ __align__(128) float d_gsum[NG * 20];    // zeroed by mlp1 each run
__device__ float d_gcnt[NG];                        // zeroed by mlp1 each run
__device__ __align__(128) float d_y1[NG * 128];
__device__ __align__(128) float d_y2[NG * 32];
__device__ float d_stat1[2 * 128];
__device__ float d_stat2[2 * 32];

// ---------------- packed f32x2 helpers ----------------
__device__ __forceinline__ ull dup2(float x) {
    ull r; asm("mov.b64 %0, {%1, %1};" : "=l"(r) : "f"(x)); return r;
}
__device__ __forceinline__ ull pk2(float lo, float hi) {
    ull r; asm("mov.b64 %0, {%1, %2};" : "=l"(r) : "f"(lo), "f"(hi)); return r;
}
__device__ __forceinline__ void fma2(ull& d, ull a, ull b) {
    asm("fma.rn.f32x2 %0, %1, %2, %0;" : "+l"(d) : "l"(a), "l"(b));
}
__device__ __forceinline__ float f2lo(ull v) { return __uint_as_float((unsigned)v); }
__device__ __forceinline__ float f2hi(ull v) { return __uint_as_float((unsigned)(v >> 32)); }

// ---------------- degree histogram: 4 edges/thread ----------------
__global__ void deg_kernel(const int* __restrict__ dst) {
    int t = blockIdx.x * blockDim.x + threadIdx.x;
    int e = t * 4;
    if (e + 3 >= NE) {
        for (; e < NE; e++) atomicAdd(&d_deg[dst[e]], 1);
        return;
    }
    int4 d = *(const int4*)(dst + e);
    atomicAdd(&d_deg[d.x], 1);
    atomicAdd(&d_deg[d.y], 1);
    atomicAdd(&d_deg[d.z], 1);
    atomicAdd(&d_deg[d.w], 1);
}

// ---------------- scan phase A: per-block sums (98 x 1024) ----------------
__global__ void __launch_bounds__(1024) sumA_kernel() {
    int b = blockIdx.x;
    int t = threadIdx.x;
    int i = b * 1024 + t;
    int v = (i < NN) ? d_deg[i] : 0;
#pragma unroll
    for (int o = 16; o > 0; o >>= 1) v += __shfl_down_sync(0xffffffffu, v, o);
    __shared__ int ws[32];
    if ((t & 31) == 0) ws[t >> 5] = v;
    __syncthreads();
    if (t < 32) {
        int s = ws[t];
#pragma unroll
        for (int o = 16; o > 0; o >>= 1) s += __shfl_down_sync(0xffffffffu, s, o);
        if (t == 0) d_bsum[b] = s;
    }
}

// ---------------- scan phase C: local scan + own prefix; zeroes d_deg ----------------
__global__ void __launch_bounds__(1024) scanC_kernel() {
    int b = blockIdx.x;
    int t = threadIdx.x;
    int i = b * 1024 + t;
    int v = (i < NN) ? d_deg[i] : 0;
    int lane = t & 31, w = t >> 5;
    int inc = v;
#pragma unroll
    for (int o = 1; o < 32; o <<= 1) {
        int u = __shfl_up_sync(0xffffffffu, inc, o);
        if (lane >= o) inc += u;
    }
    __shared__ int ws[32];
    __shared__ int sboff;
    if (lane == 31) ws[w] = inc;
    __syncthreads();
    if (w == 0) {
        int x = ws[lane];
#pragma unroll
        for (int o = 1; o < 32; o <<= 1) {
            int u = __shfl_up_sync(0xffffffffu, x, o);
            if (lane >= o) x += u;
        }
        ws[lane] = x;
    }
    if (w == 1) {
        int s = 0;
        for (int j = lane; j < b; j += 32) s += d_bsum[j];
#pragma unroll
        for (int o = 16; o > 0; o >>= 1) s += __shfl_down_sync(0xffffffffu, s, o);
        if (lane == 0) sboff = s;
    }
    __syncthreads();
    int excl = inc - v + (w > 0 ? ws[w - 1] : 0) + sboff;
    if (i < NN) {
        d_rowstart[i] = excl;
        d_cursor[i] = excl;
        d_deg[i] = 0;                      // restore zero-invariant for next run
    }
    if (b == 0 && t == 0) d_rowstart[NN] = NE;
}

// ---------------- CSR fill: 4 edges/thread ----------------
__global__ void fill_kernel(const int* __restrict__ src, const int* __restrict__ dst) {
    int t = blockIdx.x * blockDim.x + threadIdx.x;
    int e = t * 4;
    if (e + 3 >= NE) {
        for (; e < NE; e++) {
            int p = atomicAdd(&d_cursor[dst[e]], 1);
            d_csr[p] = src[e];
        }
        return;
    }
    int4 d = *(const int4*)(dst + e);
    int4 s = *(const int4*)(src + e);
    int p0 = atomicAdd(&d_cursor[d.x], 1);
    int p1 = atomicAdd(&d_cursor[d.y], 1);
    int p2 = atomicAdd(&d_cursor[d.z], 1);
    int p3 = atomicAdd(&d_cursor[d.w], 1);
    d_csr[p0] = s.x;
    d_csr[p1] = s.y;
    d_csr[p2] = s.z;
    d_csr[p3] = s.w;
}

// ---------------- proj1 (tensor cores): hp1(bf16) = feat[NN,128] @ W1[128,100] ----------------
__global__ void __launch_bounds__(256) proj1_kernel(const float* __restrict__ X,
                                                    const float* __restrict__ W1) {
    extern __shared__ char smraw[];
    __nv_bfloat16* As = (__nv_bfloat16*)smraw;            // ld 136
    __nv_bfloat16* Bs = (__nv_bfloat16*)(smraw + 34816);  // ld 120
    float* Cs = (float*)smraw;                            // ld 112 (reuse)
    const int tid = threadIdx.x;
    const int w = tid >> 5;
    const int l = tid & 31;
    const int mBase = blockIdx.x * 128;

#pragma unroll
    for (int r = 0; r < 16; r++) {
        int row = w * 16 + r;
        int gn = mBase + row;
        float4 v = (gn < NN) ? *(const float4*)(X + gn * 128 + 4 * l)
                             : make_float4(0.f, 0.f, 0.f, 0.f);
        bf4 o;
        o.a = __floats2bfloat162_rn(v.x, v.y);
        o.b = __floats2bfloat162_rn(v.z, v.w);
        *(bf4*)&As[row * 136 + 4 * l] = o;
    }
#pragma unroll
    for (int r = 0; r < 16; r++) {
        int k = w * 16 + r;
#pragma unroll
        for (int cc = 0; cc < 4; cc++) {
            int n = l + 32 * cc;
            if (n < 112)
                Bs[k * 120 + n] = __float2bfloat16((n < 100) ? W1[k * 100 + n] : 0.f);
        }
    }
    __syncthreads();

    wmma::fragment<wmma::accumulator, 16, 16, 16, float> c[7];
#pragma unroll
    for (int n = 0; n < 7; n++) wmma::fill_fragment(c[n], 0.f);
#pragma unroll
    for (int k = 0; k < 8; k++) {
        wmma::fragment<wmma::matrix_a, 16, 16, 16, __nv_bfloat16, wmma::row_major> a;
        wmma::load_matrix_sync(a, As + (w * 16) * 136 + k * 16, 136);
#pragma unroll
        for (int n = 0; n < 7; n++) {
            wmma::fragment<wmma::matrix_b, 16, 16, 16, __nv_bfloat16, wmma::row_major> b;
            wmma::load_matrix_sync(b, Bs + (k * 16) * 120 + n * 16, 120);
            wmma::mma_sync(c[n], a, b, c[n]);
        }
    }
    __syncthreads();
#pragma unroll
    for (int n = 0; n < 7; n++)
        wmma::store_matrix_sync(Cs + (w * 16) * 112 + n * 16, c[n], 112, wmma::mem_row_major);
    __syncthreads();

    if (l < 25) {
#pragma unroll
        for (int r = 0; r < 16; r++) {
            int row = w * 16 + r;
            int gn = mBase + row;
            if (gn < NN) {
                const float* p = Cs + row * 112 + l * 4;
                bf4 o;
                o.a = __floats2bfloat162_rn(p[0], p[1]);
                o.b = __floats2bfloat162_rn(p[2], p[3]);
                d_hp1b[gn * 25 + l] = o;
            }
        }
    }
}

// ---------------- gp v4: 32 nodes x 25 chunks = 800 threads, x4 unroll ----------------
// 800-thread block -> 81-reg ceiling: 4 float4 accumulators fit without spill.
// Phase 2 (320 threads = 32 nodes x 10 pairs): hp2(bf16) = h1 @ W2 via f32x2.
__global__ void __launch_bounds__(800) gp_kernel(const float* __restrict__ b1,
                                                 const float* __restrict__ W2) {
    __shared__ float h1s[32 * 104];
    __shared__ ull W2d[100 * 10];
    int tid = threadIdx.x;
    int n0 = blockIdx.x * 32;

    for (int idx = tid; idx < 1000; idx += 800) {
        float2 wv = *(const float2*)(W2 + 2 * idx);   // idx = k*10+p
        W2d[idx] = pk2(wv.x, wv.y);
    }

    int nl = tid / 25;
    int c = tid - nl * 25;
    int n = n0 + nl;
    int row0 = d_rowstart[n];
    int row1 = d_rowstart[n + 1];
    int deg = row1 - row0;

    float4 a0 = make_float4(0.f, 0.f, 0.f, 0.f);
    float4 a1 = make_float4(0.f, 0.f, 0.f, 0.f);
    float4 a2 = make_float4(0.f, 0.f, 0.f, 0.f);
    float4 a3 = make_float4(0.f, 0.f, 0.f, 0.f);
    int j = row0;
    for (; j + 3 < row1; j += 4) {
        int s0 = __ldg(&d_csr[j]);
        int s1 = __ldg(&d_csr[j + 1]);
        int s2 = __ldg(&d_csr[j + 2]);
        int s3 = __ldg(&d_csr[j + 3]);
        bf4 v0 = d_hp1b[s0 * 25 + c];
        bf4 v1 = d_hp1b[s1 * 25 + c];
        bf4 v2 = d_hp1b[s2 * 25 + c];
        bf4 v3 = d_hp1b[s3 * 25 + c];
        float2 f0a = __bfloat1622float2(v0.a), f0b = __bfloat1622float2(v0.b);
        float2 f1a = __bfloat1622float2(v1.a), f1b = __bfloat1622float2(v1.b);
        float2 f2a = __bfloat1622float2(v2.a), f2b = __bfloat1622float2(v2.b);
        float2 f3a = __bfloat1622float2(v3.a), f3b = __bfloat1622float2(v3.b);
        a0.x += f0a.x; a0.y += f0a.y; a0.z += f0b.x; a0.w += f0b.y;
        a1.x += f1a.x; a1.y += f1a.y; a1.z += f1b.x; a1.w += f1b.y;
        a2.x += f2a.x; a2.y += f2a.y; a2.z += f2b.x; a2.w += f2b.y;
        a3.x += f3a.x; a3.y += f3a.y; a3.z += f3b.x; a3.w += f3b.y;
    }
    for (; j < row1; j++) {
        int s = __ldg(&d_csr[j]);
        bf4 v = d_hp1b[s * 25 + c];
        float2 fa = __bfloat1622float2(v.a), fb = __bfloat1622float2(v.b);
        a0.x += fa.x; a0.y += fa.y; a0.z += fb.x; a0.w += fb.y;
    }
    float4 v;
    if (deg > 0) {
        float inv = 1.f / (float)deg;
        v = make_float4((a0.x + a1.x + a2.x + a3.x) * inv,
                        (a0.y + a1.y + a2.y + a3.y) * inv,
                        (a0.z + a1.z + a2.z + a3.z) * inv,
                        (a0.w + a1.w + a2.w + a3.w) * inv);
    } else {
        bf4 sv = d_hp1b[n * 25 + c];
        float2 fa = __bfloat1622float2(sv.a), fb = __bfloat1622float2(sv.b);
        v = make_float4(fa.x, fa.y, fb.x, fb.y);
    }
    float4 b = *(const float4*)(b1 + c * 4);
    float4 r = make_float4(fmaxf(v.x + b.x, 0.f), fmaxf(v.y + b.y, 0.f),
                           fmaxf(v.z + b.z, 0.f), fmaxf(v.w + b.w, 0.f));
    *(float4*)&h1s[nl * 104 + c * 4] = r;
    __syncthreads();

    if (tid < 320) {
        int node = tid / 10;
        int p = tid - node * 10;
        const float* hrow = &h1s[node * 104];
        ull acc0 = 0, acc1 = 0;
#pragma unroll 5
        for (int k = 0; k < 100; k += 2) {
            fma2(acc0, dup2(hrow[k]),     W2d[k * 10 + p]);
            fma2(acc1, dup2(hrow[k + 1]), W2d[(k + 1) * 10 + p]);
        }
        float lo = f2lo(acc0) + f2lo(acc1);
        float hi = f2hi(acc0) + f2hi(acc1);
        int gn = n0 + node;
        d_hp2b[gn * 10 + p] = __floats2bfloat162_rn(lo, hi);
    }
}

// ---------------- layer-2 gather (bf16 messages) + fused graph pooling ----------------
__global__ void __launch_bounds__(256) gather2_kernel(const float* __restrict__ b2,
                                                      const int* __restrict__ n2g) {
    const bf4* __restrict__ hp2 = (const bf4*)d_hp2b;   // 5 bf4 chunks per node
    int i = blockIdx.x * 256 + threadIdx.x;
    if (i >= NN * 5) return;
    int n = i / 5;
    int c = i - n * 5;
    int row0 = d_rowstart[n];
    int row1 = d_rowstart[n + 1];
    int deg = row1 - row0;

    float4 a0 = make_float4(0.f, 0.f, 0.f, 0.f);
    float4 a1 = make_float4(0.f, 0.f, 0.f, 0.f);
    float4 a2 = make_float4(0.f, 0.f, 0.f, 0.f);
    float4 a3 = make_float4(0.f, 0.f, 0.f, 0.f);
    int j = row0;
    for (; j + 3 < row1; j += 4) {
        int s0 = __ldg(&d_csr[j]);
        int s1 = __ldg(&d_csr[j + 1]);
        int s2 = __ldg(&d_csr[j + 2]);
        int s3 = __ldg(&d_csr[j + 3]);
        bf4 v0 = hp2[s0 * 5 + c];
        bf4 v1 = hp2[s1 * 5 + c];
        bf4 v2 = hp2[s2 * 5 + c];
        bf4 v3 = hp2[s3 * 5 + c];
        float2 f0a = __bfloat1622float2(v0.a), f0b = __bfloat1622float2(v0.b);
        float2 f1a = __bfloat1622float2(v1.a), f1b = __bfloat1622float2(v1.b);
        float2 f2a = __bfloat1622float2(v2.a), f2b = __bfloat1622float2(v2.b);
        float2 f3a = __bfloat1622float2(v3.a), f3b = __bfloat1622float2(v3.b);
        a0.x += f0a.x; a0.y += f0a.y; a0.z += f0b.x; a0.w += f0b.y;
        a1.x += f1a.x; a1.y += f1a.y; a1.z += f1b.x; a1.w += f1b.y;
        a2.x += f2a.x; a2.y += f2a.y; a2.z += f2b.x; a2.w += f2b.y;
        a3.x += f3a.x; a3.y += f3a.y; a3.z += f3b.x; a3.w += f3b.y;
    }
    for (; j < row1; j++) {
        int s = __ldg(&d_csr[j]);
        bf4 v = hp2[s * 5 + c];
        float2 fa = __bfloat1622float2(v.a), fb = __bfloat1622float2(v.b);
        a0.x += fa.x; a0.y += fa.y; a0.z += fb.x; a0.w += fb.y;
    }
    float4 v;
    if (deg > 0) {
        float inv = 1.f / (float)deg;
        v = make_float4((a0.x + a1.x + a2.x + a3.x) * inv,
                        (a0.y + a1.y + a2.y + a3.y) * inv,
                        (a0.z + a1.z + a2.z + a3.z) * inv,
                        (a0.w + a1.w + a2.w + a3.w) * inv);
    } else {
        bf4 sv = hp2[n * 5 + c];
        float2 fa = __bfloat1622float2(sv.a), fb = __bfloat1622float2(sv.b);
        v = make_float4(fa.x, fa.y, fb.x, fb.y);
    }
    float4 b = *(const float4*)(b2 + c * 4);
    float4 r = make_float4(fmaxf(v.x + b.x, 0.f), fmaxf(v.y + b.y, 0.f),
                           fmaxf(v.z + b.z, 0.f), fmaxf(v.w + b.w, 0.f));
    int g = n2g[n];
    float* gs = d_gsum + g * 20 + c * 4;
    atomicAdd(gs + 0, r.x);
    atomicAdd(gs + 1, r.y);
    atomicAdd(gs + 2, r.z);
    atomicAdd(gs + 3, r.w);
    if (c == 0) atomicAdd(&d_gcnt[g], 1.f);
}

// ---------------- mlp1: j-loop split 4-way across 512 threads; zeroes gsum/gcnt ----------------
__global__ void __launch_bounds__(512) mlp1_kernel(const float* __restrict__ sf,
                                                   const float* __restrict__ Wf1,
                                                   const float* __restrict__ bf1) {
    __shared__ float fs[640 * 8];
    __shared__ float inv[8];
    __shared__ float psum[4][4][256];   // [q][pair][2*o + lo/hi]
    int g0 = blockIdx.x * 8;
    int tid = threadIdx.x;
    if (tid < 8) inv[tid] = 1.f / fmaxf(d_gcnt[g0 + tid], 1.f);
    __syncthreads();
    for (int idx = tid; idx < 640 * 8; idx += 512) {
        int j = idx >> 3;
        int g = idx & 7;
        int k = j >> 5, s = j & 31;
        fs[idx] = d_gsum[(g0 + g) * 20 + k] * inv[g] * sf[(g0 + g) * 32 + s];
    }
    __syncthreads();
    if (tid < 8) d_gcnt[g0 + tid] = 0.f;
    if (tid < 160) d_gsum[g0 * 20 + tid] = 0.f;

    int o = tid & 127;
    int q = tid >> 7;
    ull acc[4] = {0, 0, 0, 0};
    int j0 = q * 160;
#pragma unroll 4
    for (int j = j0; j < j0 + 160; j++) {
        ull wd = dup2(Wf1[j * 128 + o]);
#pragma unroll
        for (int p = 0; p < 4; p++) {
            ull a = *(const ull*)&fs[j * 8 + 2 * p];
            fma2(acc[p], a, wd);
        }
    }
#pragma unroll
    for (int p = 0; p < 4; p++) {
        psum[q][p][2 * o]     = f2lo(acc[p]);
        psum[q][p][2 * o + 1] = f2hi(acc[p]);
    }
    __syncthreads();
    if (tid < 128) {
        float b = bf1[tid];
#pragma unroll
        for (int p = 0; p < 4; p++) {
            float lo = psum[0][p][2 * tid] + psum[1][p][2 * tid]
                     + psum[2][p][2 * tid] + psum[3][p][2 * tid];
            float hi = psum[0][p][2 * tid + 1] + psum[1][p][2 * tid + 1]
                     + psum[2][p][2 * tid + 1] + psum[3][p][2 * tid + 1];
            d_y1[(g0 + 2 * p) * 128 + tid] = lo + b;
            d_y1[(g0 + 2 * p + 1) * 128 + tid] = hi + b;
        }
    }
}

// ---------------- BatchNorm stats ----------------
template<int C>
__global__ void bnstats_kernel() {
    const float* __restrict__ Y = (C == 128) ? (const float*)d_y1 : (const float*)d_y2;
    float* __restrict__ stat = (C == 128) ? d_stat1 : d_stat2;
    int c = blockIdx.x;
    float s = 0.f, q = 0.f;
    for (int r = threadIdx.x; r < NG; r += 256) {
        float x = Y[r * C + c];
        s += x; q += x * x;
    }
#pragma unroll
    for (int o = 16; o > 0; o >>= 1) {
        s += __shfl_down_sync(0xffffffff, s, o);
        q += __shfl_down_sync(0xffffffff, q, o);
    }
    __shared__ float ss[8], sq[8];
    int w = threadIdx.x >> 5, l = threadIdx.x & 31;
    if (l == 0) { ss[w] = s; sq[w] = q; }
    __syncthreads();
    if (threadIdx.x == 0) {
        float S = 0.f, Q = 0.f;
#pragma unroll
        for (int i = 0; i < 8; i++) { S += ss[i]; Q += sq[i]; }
        float mu = S / (float)NG;
        float var = Q / (float)NG - mu * mu;
        stat[c] = mu;
        stat[C + c] = rsqrtf(var + 1e-5f);
    }
}

// ---------------- mlp2 ----------------
__global__ void mlp2_kernel(const float* __restrict__ Wf2, const float* __restrict__ bf2,
                            const float* __restrict__ g1, const float* __restrict__ be1) {
    int i = blockIdx.x * blockDim.x + threadIdx.x;
    int g = i >> 5, o = i & 31;
    float acc = 0.f;
    for (int k = 0; k < 128; k++) {
        float x = d_y1[g * 128 + k];
        x = fmaxf((x - d_stat1[k]) * d_stat1[128 + k] * g1[k] + be1[k], 0.f);
        acc += x * Wf2[k * 32 + o];
    }
    d_y2[g * 32 + o] = acc + bf2[o];
}

// ---------------- mlp3 ----------------
__global__ void mlp3_kernel(const float* __restrict__ Wf3, const float* __restrict__ bf3,
                            const float* __restrict__ g2, const float* __restrict__ be2,
                            float* __restrict__ out) {
    int i = blockIdx.x * blockDim.x + threadIdx.x;
    int g = i >> 3, o = i & 7;
    float acc = 0.f;
#pragma unroll
    for (int k = 0; k < 32; k++) {
        float x = d_y2[g * 32 + k];
        x = fmaxf((x - d_stat2[k]) * d_stat2[32 + k] * g2[k] + be2[k], 0.f);
        acc += x * Wf3[k * 8 + o];
    }
    out[i] = acc + bf3[o];
}

extern "C" void kernel_launch(void* const* d_in, const int* in_sizes, int n_in,
                              void* d_out, int out_size) {
    const float* feat = (const float*)d_in[0];
    const float* sf   = (const float*)d_in[1];
    const int*   src  = (const int*)d_in[2];
    const int*   dst  = (const int*)d_in[3];
    const int*   n2g  = (const int*)d_in[4];
    const float* W1   = (const float*)d_in[5];
    const float* b1   = (const float*)d_in[6];
    const float* W2   = (const float*)d_in[7];
    const float* b2   = (const float*)d_in[8];
    const float* Wf1  = (const float*)d_in[9];
    const float* bf1  = (const float*)d_in[10];
    const float* g1   = (const float*)d_in[11];
    const float* be1  = (const float*)d_in[12];
    const float* Wf2  = (const float*)d_in[13];
    const float* bf2  = (const float*)d_in[14];
    const float* g2   = (const float*)d_in[15];
    const float* be2  = (const float*)d_in[16];
    const float* Wf3  = (const float*)d_in[17];
    const float* bf3  = (const float*)d_in[18];
    float* out = (float*)d_out;

    static cudaStream_t s2 = nullptr;
    static cudaEvent_t evFork, evJoin;
    if (!s2) {
        cudaFuncSetAttribute(proj1_kernel,
                             cudaFuncAttributeMaxDynamicSharedMemorySize, 65536);
        cudaStreamCreateWithFlags(&s2, cudaStreamNonBlocking);
        cudaEventCreateWithFlags(&evFork, cudaEventDisableTiming);
        cudaEventCreateWithFlags(&evJoin, cudaEventDisableTiming);
    }

    // fork: CSR-build chain on s2, proj1 on the main stream — independent work
    cudaEventRecord(evFork, 0);
    cudaStreamWaitEvent(s2, evFork, 0);

    deg_kernel<<<(NE / 4 + 255) / 256, 256, 0, s2>>>(dst);         // 1
    sumA_kernel<<<98, 1024, 0, s2>>>();                            // 2
    scanC_kernel<<<98, 1024, 0, s2>>>();                           // 3
    fill_kernel<<<(NE / 4 + 255) / 256, 256, 0, s2>>>(src, dst);   // 4
    proj1_kernel<<<782, 256, 65536>>>(feat, W1);                   // 5 (main, concurrent)

    // join
    cudaEventRecord(evJoin, s2);
    cudaStreamWaitEvent(0, evJoin, 0);

    gp_kernel<<<NN / 32, 800>>>(b1, W2);                           // 6  32 nodes, x4 MLP
    gather2_kernel<<<(NN * 5 + 255) / 256, 256>>>(b2, n2g);        // 7  bf16 messages

    mlp1_kernel<<<NG / 8, 512>>>(sf, Wf1, bf1);                    // 8
    bnstats_kernel<128><<<128, 256>>>();                           // 9
    mlp2_kernel<<<NG * 32 / 256, 256>>>(Wf2, bf2, g1, be1);        // 10
    bnstats_kernel<32><<<32, 256>>>();                             // 11
    mlp3_kernel<<<NG * 8 / 256, 256>>>(Wf3, bf3, g2, be2, out);    // 12
}

// round 14
// speedup vs baseline: 1.2144x; 1.2144x over previous
#include <cuda_runtime.h>
#include <cuda_bf16.h>
#include <mma.h>

// Net_12403865551680 — 2-layer GCN + mean-pool + Kronecker BN-MLP head.
// R10: 246.9 (best). R11/R12/R13 gp redesigns ALL regressed -> R10's gp is at
//      the LTS request cap; extra MLP only costs occupancy. gp is final.
// R14: exact R10 kernels + BN-stats fused into mlp1/mlp2 (both bnstats
//      launches deleted; stat partials zeroed in deg).

using namespace nvcuda;

typedef unsigned long long ull;

#define NN 100000
#define NE 1600000
#define NG 1024

struct __align__(8) bf4 { __nv_bfloat162 a, b; };

// ---------------- scratch (zero-initialized at module load) ----------------
__device__ __align__(128) bf4   d_hp1b[NN * 25];   // feat@W1, bf16, 100 dims/node
__device__ __align__(128) float d_hp2[NN * 20];    // relu(agg)+b1 projected by W2
__device__ int   d_deg[NN];                        // zeroed by scanC each run
__device__ int   d_bsum[98];
__device__ int   d_rowstart[NN + 1];
__device__ int   d_cursor[NN];
__device__ int   d_csr[NE];
__device__ __align__(128) float d_gsum[NG * 20];   // zeroed by mlp1 each run
__device__ float d_gcnt[NG];                       // zeroed by mlp1 each run
__device__ __align__(128) float d_y1[NG * 128];
__device__ __align__(128) float d_y2[NG * 32];
__device__ float d_s1[2 * 128];   // y1 channel sum | sumsq (zeroed by deg)
__device__ float d_s2[2 * 32];    // y2 channel sum | sumsq (zeroed by deg)

// ---------------- packed f32x2 helpers ----------------
__device__ __forceinline__ ull dup2(float x) {
    ull r; asm("mov.b64 %0, {%1, %1};" : "=l"(r) : "f"(x)); return r;
}
__device__ __forceinline__ ull pk2(float lo, float hi) {
    ull r; asm("mov.b64 %0, {%1, %2};" : "=l"(r) : "f"(lo), "f"(hi)); return r;
}
__device__ __forceinline__ void fma2(ull& d, ull a, ull b) {
    asm("fma.rn.f32x2 %0, %1, %2, %0;" : "+l"(d) : "l"(a), "l"(b));
}
__device__ __forceinline__ float f2lo(ull v) { return __uint_as_float((unsigned)v); }
__device__ __forceinline__ float f2hi(ull v) { return __uint_as_float((unsigned)(v >> 32)); }

// ---------------- degree histogram: 4 edges/thread; zeroes stat partials ----------------
__global__ void deg_kernel(const int* __restrict__ dst) {
    if (blockIdx.x == 0 && threadIdx.x < 256) d_s1[threadIdx.x] = 0.f;
    if (blockIdx.x == 1 && threadIdx.x < 64)  d_s2[threadIdx.x] = 0.f;
    int t = blockIdx.x * blockDim.x + threadIdx.x;
    int e = t * 4;
    if (e + 3 >= NE) {
        for (; e < NE; e++) atomicAdd(&d_deg[dst[e]], 1);
        return;
    }
    int4 d = *(const int4*)(dst + e);
    atomicAdd(&d_deg[d.x], 1);
    atomicAdd(&d_deg[d.y], 1);
    atomicAdd(&d_deg[d.z], 1);
    atomicAdd(&d_deg[d.w], 1);
}

// ---------------- scan phase A: per-block sums (98 x 1024) ----------------
__global__ void __launch_bounds__(1024) sumA_kernel() {
    int b = blockIdx.x;
    int t = threadIdx.x;
    int i = b * 1024 + t;
    int v = (i < NN) ? d_deg[i] : 0;
#pragma unroll
    for (int o = 16; o > 0; o >>= 1) v += __shfl_down_sync(0xffffffffu, v, o);
    __shared__ int ws[32];
    if ((t & 31) == 0) ws[t >> 5] = v;
    __syncthreads();
    if (t < 32) {
        int s = ws[t];
#pragma unroll
        for (int o = 16; o > 0; o >>= 1) s += __shfl_down_sync(0xffffffffu, s, o);
        if (t == 0) d_bsum[b] = s;
    }
}

// ---------------- scan phase C: local scan + own prefix; zeroes d_deg ----------------
__global__ void __launch_bounds__(1024) scanC_kernel() {
    int b = blockIdx.x;
    int t = threadIdx.x;
    int i = b * 1024 + t;
    int v = (i < NN) ? d_deg[i] : 0;
    int lane = t & 31, w = t >> 5;
    int inc = v;
#pragma unroll
    for (int o = 1; o < 32; o <<= 1) {
        int u = __shfl_up_sync(0xffffffffu, inc, o);
        if (lane >= o) inc += u;
    }
    __shared__ int ws[32];
    __shared__ int sboff;
    if (lane == 31) ws[w] = inc;
    __syncthreads();
    if (w == 0) {
        int x = ws[lane];
#pragma unroll
        for (int o = 1; o < 32; o <<= 1) {
            int u = __shfl_up_sync(0xffffffffu, x, o);
            if (lane >= o) x += u;
        }
        ws[lane] = x;
    }
    if (w == 1) {
        int s = 0;
        for (int j = lane; j < b; j += 32) s += d_bsum[j];
#pragma unroll
        for (int o = 16; o > 0; o >>= 1) s += __shfl_down_sync(0xffffffffu, s, o);
        if (lane == 0) sboff = s;
    }
    __syncthreads();
    int excl = inc - v + (w > 0 ? ws[w - 1] : 0) + sboff;
    if (i < NN) {
        d_rowstart[i] = excl;
        d_cursor[i] = excl;
        d_deg[i] = 0;                      // restore zero-invariant for next run
    }
    if (b == 0 && t == 0) d_rowstart[NN] = NE;
}

// ---------------- CSR fill: 4 edges/thread ----------------
__global__ void fill_kernel(const int* __restrict__ src, const int* __restrict__ dst) {
    int t = blockIdx.x * blockDim.x + threadIdx.x;
    int e = t * 4;
    if (e + 3 >= NE) {
        for (; e < NE; e++) {
            int p = atomicAdd(&d_cursor[dst[e]], 1);
            d_csr[p] = src[e];
        }
        return;
    }
    int4 d = *(const int4*)(dst + e);
    int4 s = *(const int4*)(src + e);
    int p0 = atomicAdd(&d_cursor[d.x], 1);
    int p1 = atomicAdd(&d_cursor[d.y], 1);
    int p2 = atomicAdd(&d_cursor[d.z], 1);
    int p3 = atomicAdd(&d_cursor[d.w], 1);
    d_csr[p0] = s.x;
    d_csr[p1] = s.y;
    d_csr[p2] = s.z;
    d_csr[p3] = s.w;
}

// ---------------- proj1 (tensor cores): hp1(bf16) = feat[NN,128] @ W1[128,100] ----------------
__global__ void __launch_bounds__(256) proj1_kernel(const float* __restrict__ X,
                                                    const float* __restrict__ W1) {
    extern __shared__ char smraw[];
    __nv_bfloat16* As = (__nv_bfloat16*)smraw;            // ld 136
    __nv_bfloat16* Bs = (__nv_bfloat16*)(smraw + 34816);  // ld 120
    float* Cs = (float*)smraw;                            // ld 112 (reuse)
    const int tid = threadIdx.x;
    const int w = tid >> 5;
    const int l = tid & 31;
    const int mBase = blockIdx.x * 128;

#pragma unroll
    for (int r = 0; r < 16; r++) {
        int row = w * 16 + r;
        int gn = mBase + row;
        float4 v = (gn < NN) ? *(const float4*)(X + gn * 128 + 4 * l)
                             : make_float4(0.f, 0.f, 0.f, 0.f);
        bf4 o;
        o.a = __floats2bfloat162_rn(v.x, v.y);
        o.b = __floats2bfloat162_rn(v.z, v.w);
        *(bf4*)&As[row * 136 + 4 * l] = o;
    }
#pragma unroll
    for (int r = 0; r < 16; r++) {
        int k = w * 16 + r;
#pragma unroll
        for (int cc = 0; cc < 4; cc++) {
            int n = l + 32 * cc;
            if (n < 112)
                Bs[k * 120 + n] = __float2bfloat16((n < 100) ? W1[k * 100 + n] : 0.f);
        }
    }
    __syncthreads();

    wmma::fragment<wmma::accumulator, 16, 16, 16, float> c[7];
#pragma unroll
    for (int n = 0; n < 7; n++) wmma::fill_fragment(c[n], 0.f);
#pragma unroll
    for (int k = 0; k < 8; k++) {
        wmma::fragment<wmma::matrix_a, 16, 16, 16, __nv_bfloat16, wmma::row_major> a;
        wmma::load_matrix_sync(a, As + (w * 16) * 136 + k * 16, 136);
#pragma unroll
        for (int n = 0; n < 7; n++) {
            wmma::fragment<wmma::matrix_b, 16, 16, 16, __nv_bfloat16, wmma::row_major> b;
            wmma::load_matrix_sync(b, Bs + (k * 16) * 120 + n * 16, 120);
            wmma::mma_sync(c[n], a, b, c[n]);
        }
    }
    __syncthreads();
#pragma unroll
    for (int n = 0; n < 7; n++)
        wmma::store_matrix_sync(Cs + (w * 16) * 112 + n * 16, c[n], 112, wmma::mem_row_major);
    __syncthreads();

    if (l < 25) {
#pragma unroll
        for (int r = 0; r < 16; r++) {
            int row = w * 16 + r;
            int gn = mBase + row;
            if (gn < NN) {
                const float* p = Cs + row * 112 + l * 4;
                bf4 o;
                o.a = __floats2bfloat162_rn(p[0], p[1]);
                o.b = __floats2bfloat162_rn(p[2], p[3]);
                d_hp1b[gn * 25 + l] = o;
            }
        }
    }
}

// ---------------- fused layer-1 gather + proj2 (R10 exact) ----------------
__global__ void __launch_bounds__(1000) gp_kernel(const float* __restrict__ b1,
                                                  const float* __restrict__ W2) {
    __shared__ float h1s[40 * 104];
    __shared__ ull W2d[100 * 10];
    int tid = threadIdx.x;
    int n0 = blockIdx.x * 40;

    {
        float2 wv = *(const float2*)(W2 + 2 * tid);   // tid = k*10+p exactly
        W2d[tid] = pk2(wv.x, wv.y);
    }

    int nl = tid / 25;
    int c = tid - nl * 25;
    int n = n0 + nl;
    int row0 = d_rowstart[n];
    int row1 = d_rowstart[n + 1];
    int deg = row1 - row0;

    float4 a0 = make_float4(0.f, 0.f, 0.f, 0.f);
    float4 a1 = make_float4(0.f, 0.f, 0.f, 0.f);
    int j = row0;
    for (; j + 1 < row1; j += 2) {
        int s0 = __ldg(&d_csr[j]);
        int s1 = __ldg(&d_csr[j + 1]);
        bf4 v0 = d_hp1b[s0 * 25 + c];
        bf4 v1 = d_hp1b[s1 * 25 + c];
        float2 f0a = __bfloat1622float2(v0.a), f0b = __bfloat1622float2(v0.b);
        float2 f1a = __bfloat1622float2(v1.a), f1b = __bfloat1622float2(v1.b);
        a0.x += f0a.x; a0.y += f0a.y; a0.z += f0b.x; a0.w += f0b.y;
        a1.x += f1a.x; a1.y += f1a.y; a1.z += f1b.x; a1.w += f1b.y;
    }
    if (j < row1) {
        int s = __ldg(&d_csr[j]);
        bf4 v = d_hp1b[s * 25 + c];
        float2 fa = __bfloat1622float2(v.a), fb = __bfloat1622float2(v.b);
        a0.x += fa.x; a0.y += fa.y; a0.z += fb.x; a0.w += fb.y;
    }
    float4 v;
    if (deg > 0) {
        float inv = 1.f / (float)deg;
        v = make_float4((a0.x + a1.x) * inv, (a0.y + a1.y) * inv,
                        (a0.z + a1.z) * inv, (a0.w + a1.w) * inv);
    } else {
        bf4 sv = d_hp1b[n * 25 + c];
        float2 fa = __bfloat1622float2(sv.a), fb = __bfloat1622float2(sv.b);
        v = make_float4(fa.x, fa.y, fb.x, fb.y);
    }
    float4 b = *(const float4*)(b1 + c * 4);
    float4 r = make_float4(fmaxf(v.x + b.x, 0.f), fmaxf(v.y + b.y, 0.f),
                           fmaxf(v.z + b.z, 0.f), fmaxf(v.w + b.w, 0.f));
    *(float4*)&h1s[nl * 104 + c * 4] = r;
    __syncthreads();

    if (tid < 400) {
        int node = tid / 10;
        int p = tid - node * 10;
        const float* hrow = &h1s[node * 104];
        ull acc0 = 0, acc1 = 0;
#pragma unroll 5
        for (int k = 0; k < 100; k += 2) {
            fma2(acc0, dup2(hrow[k]),     W2d[k * 10 + p]);
            fma2(acc1, dup2(hrow[k + 1]), W2d[(k + 1) * 10 + p]);
        }
        float lo = f2lo(acc0) + f2lo(acc1);
        float hi = f2hi(acc0) + f2hi(acc1);
        int gn = n0 + node;
        *(float2*)(d_hp2 + gn * 20 + 2 * p) = make_float2(lo, hi);
    }
}

// ---------------- layer-2 gather + fused graph pooling (R10 exact) ----------------
__global__ void __launch_bounds__(256) gather2_kernel(const float* __restrict__ b2,
                                                      const int* __restrict__ n2g) {
    int i = blockIdx.x * 256 + threadIdx.x;
    if (i >= NN * 5) return;
    int n = i / 5;
    int c = i - n * 5;
    int row0 = d_rowstart[n];
    int row1 = d_rowstart[n + 1];
    int deg = row1 - row0;

    float4 a0 = make_float4(0.f, 0.f, 0.f, 0.f);
    float4 a1 = make_float4(0.f, 0.f, 0.f, 0.f);
    float4 a2 = make_float4(0.f, 0.f, 0.f, 0.f);
    float4 a3 = make_float4(0.f, 0.f, 0.f, 0.f);
    int j = row0;
    for (; j + 3 < row1; j += 4) {
        int s0 = __ldg(&d_csr[j]);
        int s1 = __ldg(&d_csr[j + 1]);
        int s2 = __ldg(&d_csr[j + 2]);
        int s3 = __ldg(&d_csr[j + 3]);
        float4 f0 = *(const float4*)(d_hp2 + s0 * 20 + c * 4);
        float4 f1 = *(const float4*)(d_hp2 + s1 * 20 + c * 4);
        float4 f2 = *(const float4*)(d_hp2 + s2 * 20 + c * 4);
        float4 f3 = *(const float4*)(d_hp2 + s3 * 20 + c * 4);
        a0.x += f0.x; a0.y += f0.y; a0.z += f0.z; a0.w += f0.w;
        a1.x += f1.x; a1.y += f1.y; a1.z += f1.z; a1.w += f1.w;
        a2.x += f2.x; a2.y += f2.y; a2.z += f2.z; a2.w += f2.w;
        a3.x += f3.x; a3.y += f3.y; a3.z += f3.z; a3.w += f3.w;
    }
    for (; j < row1; j++) {
        int s = __ldg(&d_csr[j]);
        float4 f = *(const float4*)(d_hp2 + s * 20 + c * 4);
        a0.x += f.x; a0.y += f.y; a0.z += f.z; a0.w += f.w;
    }
    float4 v;
    if (deg > 0) {
        float inv = 1.f / (float)deg;
        v = make_float4((a0.x + a1.x + a2.x + a3.x) * inv,
                        (a0.y + a1.y + a2.y + a3.y) * inv,
                        (a0.z + a1.z + a2.z + a3.z) * inv,
                        (a0.w + a1.w + a2.w + a3.w) * inv);
    } else {
        v = *(const float4*)(d_hp2 + n * 20 + c * 4);
    }
    float4 b = *(const float4*)(b2 + c * 4);
    float4 r = make_float4(fmaxf(v.x + b.x, 0.f), fmaxf(v.y + b.y, 0.f),
                           fmaxf(v.z + b.z, 0.f), fmaxf(v.w + b.w, 0.f));
    int g = n2g[n];
    float* gs = d_gsum + g * 20 + c * 4;
    atomicAdd(gs + 0, r.x);
    atomicAdd(gs + 1, r.y);
    atomicAdd(gs + 2, r.z);
    atomicAdd(gs + 3, r.w);
    if (c == 0) atomicAdd(&d_gcnt[g], 1.f);
}

// ---------------- mlp1: split j-loop + fused y1 channel stats ----------------
__global__ void __launch_bounds__(512) mlp1_kernel(const float* __restrict__ sf,
                                                   const float* __restrict__ Wf1,
                                                   const float* __restrict__ bf1) {
    __shared__ float fs[640 * 8];
    __shared__ float inv[8];
    __shared__ float psum[4][4][256];   // [q][pair][2*o + lo/hi]
    int g0 = blockIdx.x * 8;
    int tid = threadIdx.x;
    if (tid < 8) inv[tid] = 1.f / fmaxf(d_gcnt[g0 + tid], 1.f);
    __syncthreads();
    for (int idx = tid; idx < 640 * 8; idx += 512) {
        int j = idx >> 3;
        int g = idx & 7;
        int k = j >> 5, s = j & 31;
        fs[idx] = d_gsum[(g0 + g) * 20 + k] * inv[g] * sf[(g0 + g) * 32 + s];
    }
    __syncthreads();
    if (tid < 8) d_gcnt[g0 + tid] = 0.f;
    if (tid < 160) d_gsum[g0 * 20 + tid] = 0.f;

    int o = tid & 127;
    int q = tid >> 7;
    ull acc[4] = {0, 0, 0, 0};
    int j0 = q * 160;
#pragma unroll 4
    for (int j = j0; j < j0 + 160; j++) {
        ull wd = dup2(Wf1[j * 128 + o]);
#pragma unroll
        for (int p = 0; p < 4; p++) {
            ull a = *(const ull*)&fs[j * 8 + 2 * p];
            fma2(acc[p], a, wd);
        }
    }
#pragma unroll
    for (int p = 0; p < 4; p++) {
        psum[q][p][2 * o]     = f2lo(acc[p]);
        psum[q][p][2 * o + 1] = f2hi(acc[p]);
    }
    __syncthreads();
    if (tid < 128) {
        float b = bf1[tid];
        float s8 = 0.f, q8 = 0.f;
#pragma unroll
        for (int p = 0; p < 4; p++) {
            float lo = psum[0][p][2 * tid] + psum[1][p][2 * tid]
                     + psum[2][p][2 * tid] + psum[3][p][2 * tid] + b;
            float hi = psum[0][p][2 * tid + 1] + psum[1][p][2 * tid + 1]
                     + psum[2][p][2 * tid + 1] + psum[3][p][2 * tid + 1] + b;
            d_y1[(g0 + 2 * p) * 128 + tid] = lo;
            d_y1[(g0 + 2 * p + 1) * 128 + tid] = hi;
            s8 += lo + hi;
            q8 += lo * lo + hi * hi;
        }
        atomicAdd(&d_s1[tid], s8);
        atomicAdd(&d_s1[128 + tid], q8);
    }
}

// ---------------- mlp2: BN(y1) finalize inline + GEMM + y2 stats ----------------
__global__ void __launch_bounds__(256) mlp2_kernel(const float* __restrict__ Wf2,
                                                   const float* __restrict__ bf2,
                                                   const float* __restrict__ g1,
                                                   const float* __restrict__ be1) {
    __shared__ float gsn[128], bsn[128];
    __shared__ float ssum[32], ssq[32];
    int tid = threadIdx.x;
    if (tid < 128) {
        float s = d_s1[tid], q = d_s1[128 + tid];
        float mu = s * (1.f / (float)NG);
        float var = q * (1.f / (float)NG) - mu * mu;
        float rs = rsqrtf(var + 1e-5f);
        float gm = g1[tid] * rs;
        gsn[tid] = gm;
        bsn[tid] = be1[tid] - mu * gm;
    }
    if (tid < 32) { ssum[tid] = 0.f; ssq[tid] = 0.f; }
    __syncthreads();

    int i = blockIdx.x * 256 + tid;
    int g = i >> 5, o = i & 31;
    float acc = 0.f;
#pragma unroll 4
    for (int k = 0; k < 128; k++) {
        float x = d_y1[g * 128 + k];
        float h = fmaxf(fmaf(x, gsn[k], bsn[k]), 0.f);
        acc = fmaf(h, Wf2[k * 32 + o], acc);
    }
    float val = acc + bf2[o];
    d_y2[g * 32 + o] = val;
    atomicAdd(&ssum[o], val);
    atomicAdd(&ssq[o], val * val);
    __syncthreads();
    if (tid < 32) {
        atomicAdd(&d_s2[tid], ssum[tid]);
        atomicAdd(&d_s2[32 + tid], ssq[tid]);
    }
}

// ---------------- mlp3: BN(y2) finalize inline + final GEMM ----------------
__global__ void __launch_bounds__(256) mlp3_kernel(const float* __restrict__ Wf3,
                                                   const float* __restrict__ bf3,
                                                   const float* __restrict__ g2,
                                                   const float* __restrict__ be2,
                                                   float* __restrict__ out) {
    __shared__ float gsn[32], bsn[32];
    int tid = threadIdx.x;
    if (tid < 32) {
        float s = d_s2[tid], q = d_s2[32 + tid];
        float mu = s * (1.f / (float)NG);
        float var = q * (1.f / (float)NG) - mu * mu;
        float rs = rsqrtf(var + 1e-5f);
        float gm = g2[tid] * rs;
        gsn[tid] = gm;
        bsn[tid] = be2[tid] - mu * gm;
    }
    __syncthreads();

    int i = blockIdx.x * 256 + tid;
    int g = i >> 3, o = i & 7;
    float acc = 0.f;
#pragma unroll
    for (int k = 0; k < 32; k++) {
        float x = d_y2[g * 32 + k];
        float h = fmaxf(fmaf(x, gsn[k], bsn[k]), 0.f);
        acc = fmaf(h, Wf3[k * 8 + o], acc);
    }
    out[i] = acc + bf3[o];
}

extern "C" void kernel_launch(void* const* d_in, const int* in_sizes, int n_in,
                              void* d_out, int out_size) {
    const float* feat = (const float*)d_in[0];
    const float* sf   = (const float*)d_in[1];
    const int*   src  = (const int*)d_in[2];
    const int*   dst  = (const int*)d_in[3];
    const int*   n2g  = (const int*)d_in[4];
    const float* W1   = (const float*)d_in[5];
    const float* b1   = (const float*)d_in[6];
    const float* W2   = (const float*)d_in[7];
    const float* b2   = (const float*)d_in[8];
    const float* Wf1  = (const float*)d_in[9];
    const float* bf1  = (const float*)d_in[10];
    const float* g1   = (const float*)d_in[11];
    const float* be1  = (const float*)d_in[12];
    const float* Wf2  = (const float*)d_in[13];
    const float* bf2  = (const float*)d_in[14];
    const float* g2   = (const float*)d_in[15];
    const float* be2  = (const float*)d_in[16];
    const float* Wf3  = (const float*)d_in[17];
    const float* bf3  = (const float*)d_in[18];
    float* out = (float*)d_out;

    static cudaStream_t s2 = nullptr;
    static cudaEvent_t evFork, evJoin;
    if (!s2) {
        cudaFuncSetAttribute(proj1_kernel,
                             cudaFuncAttributeMaxDynamicSharedMemorySize, 65536);
        cudaStreamCreateWithFlags(&s2, cudaStreamNonBlocking);
        cudaEventCreateWithFlags(&evFork, cudaEventDisableTiming);
        cudaEventCreateWithFlags(&evJoin, cudaEventDisableTiming);
    }

    // fork: CSR-build chain on s2, proj1 on the main stream — independent work
    cudaEventRecord(evFork, 0);
    cudaStreamWaitEvent(s2, evFork, 0);

    deg_kernel<<<(NE / 4 + 255) / 256, 256, 0, s2>>>(dst);         // 1
    sumA_kernel<<<98, 1024, 0, s2>>>();                            // 2
    scanC_kernel<<<98, 1024, 0, s2>>>();                           // 3
    fill_kernel<<<(NE / 4 + 255) / 256, 256, 0, s2>>>(src, dst);   // 4  (ncu slot)
    proj1_kernel<<<782, 256, 65536>>>(feat, W1);                   // 5  (main, concurrent)

    // join
    cudaEventRecord(evJoin, s2);
    cudaStreamWaitEvent(0, evJoin, 0);

    gp_kernel<<<NN / 40, 1000>>>(b1, W2);                          // 6
    gather2_kernel<<<(NN * 5 + 255) / 256, 256>>>(b2, n2g);        // 7

    mlp1_kernel<<<NG / 8, 512>>>(sf, Wf1, bf1);                    // 8
    mlp2_kernel<<<NG * 32 / 256, 256>>>(Wf2, bf2, g1, be1);        // 9
    mlp3_kernel<<<NG * 8 / 256, 256>>>(Wf3, bf3, g2, be2, out);    // 10
}

// round 15
// speedup vs baseline: 1.2228x; 1.0069x over previous
#include <cuda_runtime.h>
#include <cuda_bf16.h>
#include <mma.h>

// Net_12403865551680 — 2-layer GCN + mean-pool + Kronecker BN-MLP head.
// R14: 228.8 (best). Diagnosis: gp is LSU-ISSUE-bound (40M discrete 8B gathers
//      ~= 77us of pure load-issue) — why all MLP/warp restructures failed.
// R15: hp1 padded to 104 dims (13 x 16B chunks); gp gathers 16B loads
//      (20.8M loads, half the issue time). 50-node/650-thread blocks.
//      All other kernels identical to R14.

using namespace nvcuda;

typedef unsigned long long ull;

#define NN 100000
#define NE 1600000
#define NG 1024

struct __align__(8) bf4 { __nv_bfloat162 a, b; };
struct __align__(16) bf8 { __nv_bfloat162 a, b, c, d; };

// ---------------- scratch (zero-initialized at module load) ----------------
__device__ __align__(128) bf8   d_hp1b[NN * 13];   // feat@W1, bf16, 104 dims/node (100 + 4 zero pad)
__device__ __align__(128) float d_hp2[NN * 20];    // relu(agg)+b1 projected by W2
__device__ int   d_deg[NN];                        // zeroed by scanC each run
__device__ int   d_bsum[98];
__device__ int   d_rowstart[NN + 1];
__device__ int   d_cursor[NN];
__device__ int   d_csr[NE];
__device__ __align__(128) float d_gsum[NG * 20];   // zeroed by mlp1 each run
__device__ float d_gcnt[NG];                       // zeroed by mlp1 each run
__device__ __align__(128) float d_y1[NG * 128];
__device__ __align__(128) float d_y2[NG * 32];
__device__ float d_s1[2 * 128];   // y1 channel sum | sumsq (zeroed by deg)
__device__ float d_s2[2 * 32];    // y2 channel sum | sumsq (zeroed by deg)

// ---------------- packed f32x2 helpers ----------------
__device__ __forceinline__ ull dup2(float x) {
    ull r; asm("mov.b64 %0, {%1, %1};" : "=l"(r) : "f"(x)); return r;
}
__device__ __forceinline__ ull pk2(float lo, float hi) {
    ull r; asm("mov.b64 %0, {%1, %2};" : "=l"(r) : "f"(lo), "f"(hi)); return r;
}
__device__ __forceinline__ void fma2(ull& d, ull a, ull b) {
    asm("fma.rn.f32x2 %0, %1, %2, %0;" : "+l"(d) : "l"(a), "l"(b));
}
__device__ __forceinline__ float f2lo(ull v) { return __uint_as_float((unsigned)v); }
__device__ __forceinline__ float f2hi(ull v) { return __uint_as_float((unsigned)(v >> 32)); }

// ---------------- degree histogram: 4 edges/thread; zeroes stat partials ----------------
__global__ void deg_kernel(const int* __restrict__ dst) {
    if (blockIdx.x == 0 && threadIdx.x < 256) d_s1[threadIdx.x] = 0.f;
    if (blockIdx.x == 1 && threadIdx.x < 64)  d_s2[threadIdx.x] = 0.f;
    int t = blockIdx.x * blockDim.x + threadIdx.x;
    int e = t * 4;
    if (e + 3 >= NE) {
        for (; e < NE; e++) atomicAdd(&d_deg[dst[e]], 1);
        return;
    }
    int4 d = *(const int4*)(dst + e);
    atomicAdd(&d_deg[d.x], 1);
    atomicAdd(&d_deg[d.y], 1);
    atomicAdd(&d_deg[d.z], 1);
    atomicAdd(&d_deg[d.w], 1);
}

// ---------------- scan phase A: per-block sums (98 x 1024) ----------------
__global__ void __launch_bounds__(1024) sumA_kernel() {
    int b = blockIdx.x;
    int t = threadIdx.x;
    int i = b * 1024 + t;
    int v = (i < NN) ? d_deg[i] : 0;
#pragma unroll
    for (int o = 16; o > 0; o >>= 1) v += __shfl_down_sync(0xffffffffu, v, o);
    __shared__ int ws[32];
    if ((t & 31) == 0) ws[t >> 5] = v;
    __syncthreads();
    if (t < 32) {
        int s = ws[t];
#pragma unroll
        for (int o = 16; o > 0; o >>= 1) s += __shfl_down_sync(0xffffffffu, s, o);
        if (t == 0) d_bsum[b] = s;
    }
}

// ---------------- scan phase C: local scan + own prefix; zeroes d_deg ----------------
__global__ void __launch_bounds__(1024) scanC_kernel() {
    int b = blockIdx.x;
    int t = threadIdx.x;
    int i = b * 1024 + t;
    int v = (i < NN) ? d_deg[i] : 0;
    int lane = t & 31, w = t >> 5;
    int inc = v;
#pragma unroll
    for (int o = 1; o < 32; o <<= 1) {
        int u = __shfl_up_sync(0xffffffffu, inc, o);
        if (lane >= o) inc += u;
    }
    __shared__ int ws[32];
    __shared__ int sboff;
    if (lane == 31) ws[w] = inc;
    __syncthreads();
    if (w == 0) {
        int x = ws[lane];
#pragma unroll
        for (int o = 1; o < 32; o <<= 1) {
            int u = __shfl_up_sync(0xffffffffu, x, o);
            if (lane >= o) x += u;
        }
        ws[lane] = x;
    }
    if (w == 1) {
        int s = 0;
        for (int j = lane; j < b; j += 32) s += d_bsum[j];
#pragma unroll
        for (int o = 16; o > 0; o >>= 1) s += __shfl_down_sync(0xffffffffu, s, o);
        if (lane == 0) sboff = s;
    }
    __syncthreads();
    int excl = inc - v + (w > 0 ? ws[w - 1] : 0) + sboff;
    if (i < NN) {
        d_rowstart[i] = excl;
        d_cursor[i] = excl;
        d_deg[i] = 0;                      // restore zero-invariant for next run
    }
    if (b == 0 && t == 0) d_rowstart[NN] = NE;
}

// ---------------- CSR fill: 4 edges/thread ----------------
__global__ void fill_kernel(const int* __restrict__ src, const int* __restrict__ dst) {
    int t = blockIdx.x * blockDim.x + threadIdx.x;
    int e = t * 4;
    if (e + 3 >= NE) {
        for (; e < NE; e++) {
            int p = atomicAdd(&d_cursor[dst[e]], 1);
            d_csr[p] = src[e];
        }
        return;
    }
    int4 d = *(const int4*)(dst + e);
    int4 s = *(const int4*)(src + e);
    int p0 = atomicAdd(&d_cursor[d.x], 1);
    int p1 = atomicAdd(&d_cursor[d.y], 1);
    int p2 = atomicAdd(&d_cursor[d.z], 1);
    int p3 = atomicAdd(&d_cursor[d.w], 1);
    d_csr[p0] = s.x;
    d_csr[p1] = s.y;
    d_csr[p2] = s.z;
    d_csr[p3] = s.w;
}

// ---------------- proj1 (tensor cores): hp1(bf16,padded) = feat @ W1 ----------------
__global__ void __launch_bounds__(256) proj1_kernel(const float* __restrict__ X,
                                                    const float* __restrict__ W1) {
    extern __shared__ char smraw[];
    __nv_bfloat16* As = (__nv_bfloat16*)smraw;            // ld 136
    __nv_bfloat16* Bs = (__nv_bfloat16*)(smraw + 34816);  // ld 120
    float* Cs = (float*)smraw;                            // ld 112 (reuse)
    const int tid = threadIdx.x;
    const int w = tid >> 5;
    const int l = tid & 31;
    const int mBase = blockIdx.x * 128;

#pragma unroll
    for (int r = 0; r < 16; r++) {
        int row = w * 16 + r;
        int gn = mBase + row;
        float4 v = (gn < NN) ? *(const float4*)(X + gn * 128 + 4 * l)
                             : make_float4(0.f, 0.f, 0.f, 0.f);
        bf4 o;
        o.a = __floats2bfloat162_rn(v.x, v.y);
        o.b = __floats2bfloat162_rn(v.z, v.w);
        *(bf4*)&As[row * 136 + 4 * l] = o;
    }
#pragma unroll
    for (int r = 0; r < 16; r++) {
        int k = w * 16 + r;
#pragma unroll
        for (int cc = 0; cc < 4; cc++) {
            int n = l + 32 * cc;
            if (n < 112)
                Bs[k * 120 + n] = __float2bfloat16((n < 100) ? W1[k * 100 + n] : 0.f);
        }
    }
    __syncthreads();

    wmma::fragment<wmma::accumulator, 16, 16, 16, float> c[7];
#pragma unroll
    for (int n = 0; n < 7; n++) wmma::fill_fragment(c[n], 0.f);
#pragma unroll
    for (int k = 0; k < 8; k++) {
        wmma::fragment<wmma::matrix_a, 16, 16, 16, __nv_bfloat16, wmma::row_major> a;
        wmma::load_matrix_sync(a, As + (w * 16) * 136 + k * 16, 136);
#pragma unroll
        for (int n = 0; n < 7; n++) {
            wmma::fragment<wmma::matrix_b, 16, 16, 16, __nv_bfloat16, wmma::row_major> b;
            wmma::load_matrix_sync(b, Bs + (k * 16) * 120 + n * 16, 120);
            wmma::mma_sync(c[n], a, b, c[n]);
        }
    }
    __syncthreads();
#pragma unroll
    for (int n = 0; n < 7; n++)
        wmma::store_matrix_sync(Cs + (w * 16) * 112 + n * 16, c[n], 112, wmma::mem_row_major);
    __syncthreads();

    // epilogue: 26 bf4 chunks/row (104 dims); chunk 25 = zeros (cols 100..103)
    if (l < 26) {
        bf4* outRowBase = (bf4*)d_hp1b;
#pragma unroll
        for (int r = 0; r < 16; r++) {
            int row = w * 16 + r;
            int gn = mBase + row;
            if (gn < NN) {
                bf4 o;
                if (l < 25) {
                    const float* p = Cs + row * 112 + l * 4;
                    o.a = __floats2bfloat162_rn(p[0], p[1]);
                    o.b = __floats2bfloat162_rn(p[2], p[3]);
                } else {
                    o.a = __floats2bfloat162_rn(0.f, 0.f);
                    o.b = __floats2bfloat162_rn(0.f, 0.f);
                }
                outRowBase[gn * 26 + l] = o;
            }
        }
    }
}

// ---------------- fused layer-1 gather + proj2 (16B gathers) ----------------
// 50 nodes x 13 chunks (8 dims each, 104 padded) = 650 threads. x2 edge unroll.
// Phase 2 (500 threads = 50 nodes x 10 pairs): hp2 = h1 @ W2 via f32x2.
__global__ void __launch_bounds__(650) gp_kernel(const float* __restrict__ b1,
                                                 const float* __restrict__ W2) {
    __shared__ float h1s[50 * 104];
    __shared__ ull W2d[100 * 10];
    __shared__ float b1s[104];
    int tid = threadIdx.x;
    int n0 = blockIdx.x * 50;

    for (int idx = tid; idx < 1000; idx += 650) {
        float2 wv = *(const float2*)(W2 + 2 * idx);   // idx = k*10+p
        W2d[idx] = pk2(wv.x, wv.y);
    }
    if (tid < 104) b1s[tid] = (tid < 100) ? b1[tid] : 0.f;
    __syncthreads();

    int nl = tid / 13;
    int c = tid - nl * 13;
    int n = n0 + nl;

    if (nl < 50) {
        int row0 = d_rowstart[n];
        int row1 = d_rowstart[n + 1];
        int deg = row1 - row0;

        float a0[8] = {0.f, 0.f, 0.f, 0.f, 0.f, 0.f, 0.f, 0.f};
        float a1[8] = {0.f, 0.f, 0.f, 0.f, 0.f, 0.f, 0.f, 0.f};
        int j = row0;
        for (; j + 1 < row1; j += 2) {
            int s0 = __ldg(&d_csr[j]);
            int s1 = __ldg(&d_csr[j + 1]);
            bf8 v0 = d_hp1b[s0 * 13 + c];
            bf8 v1 = d_hp1b[s1 * 13 + c];
            float2 p0 = __bfloat1622float2(v0.a), p1 = __bfloat1622float2(v0.b);
            float2 p2 = __bfloat1622float2(v0.c), p3 = __bfloat1622float2(v0.d);
            float2 q0 = __bfloat1622float2(v1.a), q1 = __bfloat1622float2(v1.b);
            float2 q2 = __bfloat1622float2(v1.c), q3 = __bfloat1622float2(v1.d);
            a0[0] += p0.x; a0[1] += p0.y; a0[2] += p1.x; a0[3] += p1.y;
            a0[4] += p2.x; a0[5] += p2.y; a0[6] += p3.x; a0[7] += p3.y;
            a1[0] += q0.x; a1[1] += q0.y; a1[2] += q1.x; a1[3] += q1.y;
            a1[4] += q2.x; a1[5] += q2.y; a1[6] += q3.x; a1[7] += q3.y;
        }
        if (j < row1) {
            int s = __ldg(&d_csr[j]);
            bf8 v = d_hp1b[s * 13 + c];
            float2 p0 = __bfloat1622float2(v.a), p1 = __bfloat1622float2(v.b);
            float2 p2 = __bfloat1622float2(v.c), p3 = __bfloat1622float2(v.d);
            a0[0] += p0.x; a0[1] += p0.y; a0[2] += p1.x; a0[3] += p1.y;
            a0[4] += p2.x; a0[5] += p2.y; a0[6] += p3.x; a0[7] += p3.y;
        }
        float r[8];
        if (deg > 0) {
            float inv = 1.f / (float)deg;
#pragma unroll
            for (int i = 0; i < 8; i++) r[i] = (a0[i] + a1[i]) * inv;
        } else {
            bf8 sv = d_hp1b[n * 13 + c];
            float2 p0 = __bfloat1622float2(sv.a), p1 = __bfloat1622float2(sv.b);
            float2 p2 = __bfloat1622float2(sv.c), p3 = __bfloat1622float2(sv.d);
            r[0] = p0.x; r[1] = p0.y; r[2] = p1.x; r[3] = p1.y;
            r[4] = p2.x; r[5] = p2.y; r[6] = p3.x; r[7] = p3.y;
        }
        float4 w0, w1;
        const float* bb = &b1s[c * 8];
        w0.x = fmaxf(r[0] + bb[0], 0.f);
        w0.y = fmaxf(r[1] + bb[1], 0.f);
        w0.z = fmaxf(r[2] + bb[2], 0.f);
        w0.w = fmaxf(r[3] + bb[3], 0.f);
        w1.x = fmaxf(r[4] + bb[4], 0.f);
        w1.y = fmaxf(r[5] + bb[5], 0.f);
        w1.z = fmaxf(r[6] + bb[6], 0.f);
        w1.w = fmaxf(r[7] + bb[7], 0.f);
        *(float4*)&h1s[nl * 104 + c * 8]     = w0;
        *(float4*)&h1s[nl * 104 + c * 8 + 4] = w1;
    }
    __syncthreads();

    if (tid < 500) {
        int node = tid / 10;
        int p = tid - node * 10;
        const float* hrow = &h1s[node * 104];
        ull acc0 = 0, acc1 = 0;
#pragma unroll 5
        for (int k = 0; k < 100; k += 2) {
            fma2(acc0, dup2(hrow[k]),     W2d[k * 10 + p]);
            fma2(acc1, dup2(hrow[k + 1]), W2d[(k + 1) * 10 + p]);
        }
        float lo = f2lo(acc0) + f2lo(acc1);
        float hi = f2hi(acc0) + f2hi(acc1);
        int gn = n0 + node;
        *(float2*)(d_hp2 + gn * 20 + 2 * p) = make_float2(lo, hi);
    }
}

// ---------------- layer-2 gather + fused graph pooling (R14 exact) ----------------
__global__ void __launch_bounds__(256) gather2_kernel(const float* __restrict__ b2,
                                                      const int* __restrict__ n2g) {
    int i = blockIdx.x * 256 + threadIdx.x;
    if (i >= NN * 5) return;
    int n = i / 5;
    int c = i - n * 5;
    int row0 = d_rowstart[n];
    int row1 = d_rowstart[n + 1];
    int deg = row1 - row0;

    float4 a0 = make_float4(0.f, 0.f, 0.f, 0.f);
    float4 a1 = make_float4(0.f, 0.f, 0.f, 0.f);
    float4 a2 = make_float4(0.f, 0.f, 0.f, 0.f);
    float4 a3 = make_float4(0.f, 0.f, 0.f, 0.f);
    int j = row0;
    for (; j + 3 < row1; j += 4) {
        int s0 = __ldg(&d_csr[j]);
        int s1 = __ldg(&d_csr[j + 1]);
        int s2 = __ldg(&d_csr[j + 2]);
        int s3 = __ldg(&d_csr[j + 3]);
        float4 f0 = *(const float4*)(d_hp2 + s0 * 20 + c * 4);
        float4 f1 = *(const float4*)(d_hp2 + s1 * 20 + c * 4);
        float4 f2 = *(const float4*)(d_hp2 + s2 * 20 + c * 4);
        float4 f3 = *(const float4*)(d_hp2 + s3 * 20 + c * 4);
        a0.x += f0.x; a0.y += f0.y; a0.z += f0.z; a0.w += f0.w;
        a1.x += f1.x; a1.y += f1.y; a1.z += f1.z; a1.w += f1.w;
        a2.x += f2.x; a2.y += f2.y; a2.z += f2.z; a2.w += f2.w;
        a3.x += f3.x; a3.y += f3.y; a3.z += f3.z; a3.w += f3.w;
    }
    for (; j < row1; j++) {
        int s = __ldg(&d_csr[j]);
        float4 f = *(const float4*)(d_hp2 + s * 20 + c * 4);
        a0.x += f.x; a0.y += f.y; a0.z += f.z; a0.w += f.w;
    }
    float4 v;
    if (deg > 0) {
        float inv = 1.f / (float)deg;
        v = make_float4((a0.x + a1.x + a2.x + a3.x) * inv,
                        (a0.y + a1.y + a2.y + a3.y) * inv,
                        (a0.z + a1.z + a2.z + a3.z) * inv,
                        (a0.w + a1.w + a2.w + a3.w) * inv);
    } else {
        v = *(const float4*)(d_hp2 + n * 20 + c * 4);
    }
    float4 b = *(const float4*)(b2 + c * 4);
    float4 r = make_float4(fmaxf(v.x + b.x, 0.f), fmaxf(v.y + b.y, 0.f),
                           fmaxf(v.z + b.z, 0.f), fmaxf(v.w + b.w, 0.f));
    int g = n2g[n];
    float* gs = d_gsum + g * 20 + c * 4;
    atomicAdd(gs + 0, r.x);
    atomicAdd(gs + 1, r.y);
    atomicAdd(gs + 2, r.z);
    atomicAdd(gs + 3, r.w);
    if (c == 0) atomicAdd(&d_gcnt[g], 1.f);
}

// ---------------- mlp1: split j-loop + fused y1 channel stats ----------------
__global__ void __launch_bounds__(512) mlp1_kernel(const float* __restrict__ sf,
                                                   const float* __restrict__ Wf1,
                                                   const float* __restrict__ bf1) {
    __shared__ float fs[640 * 8];
    __shared__ float inv[8];
    __shared__ float psum[4][4][256];   // [q][pair][2*o + lo/hi]
    int g0 = blockIdx.x * 8;
    int tid = threadIdx.x;
    if (tid < 8) inv[tid] = 1.f / fmaxf(d_gcnt[g0 + tid], 1.f);
    __syncthreads();
    for (int idx = tid; idx < 640 * 8; idx += 512) {
        int j = idx >> 3;
        int g = idx & 7;
        int k = j >> 5, s = j & 31;
        fs[idx] = d_gsum[(g0 + g) * 20 + k] * inv[g] * sf[(g0 + g) * 32 + s];
    }
    __syncthreads();
    if (tid < 8) d_gcnt[g0 + tid] = 0.f;
    if (tid < 160) d_gsum[g0 * 20 + tid] = 0.f;

    int o = tid & 127;
    int q = tid >> 7;
    ull acc[4] = {0, 0, 0, 0};
    int j0 = q * 160;
#pragma unroll 4
    for (int j = j0; j < j0 + 160; j++) {
        ull wd = dup2(Wf1[j * 128 + o]);
#pragma unroll
        for (int p = 0; p < 4; p++) {
            ull a = *(const ull*)&fs[j * 8 + 2 * p];
            fma2(acc[p], a, wd);
        }
    }
#pragma unroll
    for (int p = 0; p < 4; p++) {
        psum[q][p][2 * o]     = f2lo(acc[p]);
        psum[q][p][2 * o + 1] = f2hi(acc[p]);
    }
    __syncthreads();
    if (tid < 128) {
        float b = bf1[tid];
        float s8 = 0.f, q8 = 0.f;
#pragma unroll
        for (int p = 0; p < 4; p++) {
            float lo = psum[0][p][2 * tid] + psum[1][p][2 * tid]
                     + psum[2][p][2 * tid] + psum[3][p][2 * tid] + b;
            float hi = psum[0][p][2 * tid + 1] + psum[1][p][2 * tid + 1]
                     + psum[2][p][2 * tid + 1] + psum[3][p][2 * tid + 1] + b;
            d_y1[(g0 + 2 * p) * 128 + tid] = lo;
            d_y1[(g0 + 2 * p + 1) * 128 + tid] = hi;
            s8 += lo + hi;
            q8 += lo * lo + hi * hi;
        }
        atomicAdd(&d_s1[tid], s8);
        atomicAdd(&d_s1[128 + tid], q8);
    }
}

// ---------------- mlp2: BN(y1) finalize inline + GEMM + y2 stats ----------------
__global__ void __launch_bounds__(256) mlp2_kernel(const float* __restrict__ Wf2,
                                                   const float* __restrict__ bf2,
                                                   const float* __restrict__ g1,
                                                   const float* __restrict__ be1) {
    __shared__ float gsn[128], bsn[128];
    __shared__ float ssum[32], ssq[32];
    int tid = threadIdx.x;
    if (tid < 128) {
        float s = d_s1[tid], q = d_s1[128 + tid];
        float mu = s * (1.f / (float)NG);
        float var = q * (1.f / (float)NG) - mu * mu;
        float rs = rsqrtf(var + 1e-5f);
        float gm = g1[tid] * rs;
        gsn[tid] = gm;
        bsn[tid] = be1[tid] - mu * gm;
    }
    if (tid < 32) { ssum[tid] = 0.f; ssq[tid] = 0.f; }
    __syncthreads();

    int i = blockIdx.x * 256 + tid;
    int g = i >> 5, o = i & 31;
    float acc = 0.f;
#pragma unroll 4
    for (int k = 0; k < 128; k++) {
        float x = d_y1[g * 128 + k];
        float h = fmaxf(fmaf(x, gsn[k], bsn[k]), 0.f);
        acc = fmaf(h, Wf2[k * 32 + o], acc);
    }
    float val = acc + bf2[o];
    d_y2[g * 32 + o] = val;
    atomicAdd(&ssum[o], val);
    atomicAdd(&ssq[o], val * val);
    __syncthreads();
    if (tid < 32) {
        atomicAdd(&d_s2[tid], ssum[tid]);
        atomicAdd(&d_s2[32 + tid], ssq[tid]);
    }
}

// ---------------- mlp3: BN(y2) finalize inline + final GEMM ----------------
__global__ void __launch_bounds__(256) mlp3_kernel(const float* __restrict__ Wf3,
                                                   const float* __restrict__ bf3,
                                                   const float* __restrict__ g2,
                                                   const float* __restrict__ be2,
                                                   float* __restrict__ out) {
    __shared__ float gsn[32], bsn[32];
    int tid = threadIdx.x;
    if (tid < 32) {
        float s = d_s2[tid], q = d_s2[32 + tid];
        float mu = s * (1.f / (float)NG);
        float var = q * (1.f / (float)NG) - mu * mu;
        float rs = rsqrtf(var + 1e-5f);
        float gm = g2[tid] * rs;
        gsn[tid] = gm;
        bsn[tid] = be2[tid] - mu * gm;
    }
    __syncthreads();

    int i = blockIdx.x * 256 + tid;
    int g = i >> 3, o = i & 7;
    float acc = 0.f;
#pragma unroll
    for (int k = 0; k < 32; k++) {
        float x = d_y2[g * 32 + k];
        float h = fmaxf(fmaf(x, gsn[k], bsn[k]), 0.f);
        acc = fmaf(h, Wf3[k * 8 + o], acc);
    }
    out[i] = acc + bf3[o];
}

extern "C" void kernel_launch(void* const* d_in, const int* in_sizes, int n_in,
                              void* d_out, int out_size) {
    const float* feat = (const float*)d_in[0];
    const float* sf   = (const float*)d_in[1];
    const int*   src  = (const int*)d_in[2];
    const int*   dst  = (const int*)d_in[3];
    const int*   n2g  = (const int*)d_in[4];
    const float* W1   = (const float*)d_in[5];
    const float* b1   = (const float*)d_in[6];
    const float* W2   = (const float*)d_in[7];
    const float* b2   = (const float*)d_in[8];
    const float* Wf1  = (const float*)d_in[9];
    const float* bf1  = (const float*)d_in[10];
    const float* g1   = (const float*)d_in[11];
    const float* be1  = (const float*)d_in[12];
    const float* Wf2  = (const float*)d_in[13];
    const float* bf2  = (const float*)d_in[14];
    const float* g2   = (const float*)d_in[15];
    const float* be2  = (const float*)d_in[16];
    const float* Wf3  = (const float*)d_in[17];
    const float* bf3  = (const float*)d_in[18];
    float* out = (float*)d_out;

    static cudaStream_t s2 = nullptr;
    static cudaEvent_t evFork, evJoin;
    if (!s2) {
        cudaFuncSetAttribute(proj1_kernel,
                             cudaFuncAttributeMaxDynamicSharedMemorySize, 65536);
        cudaStreamCreateWithFlags(&s2, cudaStreamNonBlocking);
        cudaEventCreateWithFlags(&evFork, cudaEventDisableTiming);
        cudaEventCreateWithFlags(&evJoin, cudaEventDisableTiming);
    }

    // fork: CSR-build chain on s2, proj1 on the main stream — independent work
    cudaEventRecord(evFork, 0);
    cudaStreamWaitEvent(s2, evFork, 0);

    deg_kernel<<<(NE / 4 + 255) / 256, 256, 0, s2>>>(dst);         // 1
    sumA_kernel<<<98, 1024, 0, s2>>>();                            // 2
    scanC_kernel<<<98, 1024, 0, s2>>>();                           // 3
    fill_kernel<<<(NE / 4 + 255) / 256, 256, 0, s2>>>(src, dst);   // 4  (ncu slot)
    proj1_kernel<<<782, 256, 65536>>>(feat, W1);                   // 5  (main, concurrent)

    // join
    cudaEventRecord(evJoin, s2);
    cudaStreamWaitEvent(0, evJoin, 0);

    gp_kernel<<<NN / 50, 650>>>(b1, W2);                           // 6  16B gathers
    gather2_kernel<<<(NN * 5 + 255) / 256, 256>>>(b2, n2g);        // 7

    mlp1_kernel<<<NG / 8, 512>>>(sf, Wf1, bf1);                    // 8
    mlp2_kernel<<<NG * 32 / 256, 256>>>(Wf2, bf2, g1, be1);        // 9
    mlp3_kernel<<<NG * 8 / 256, 256>>>(Wf3, bf3, g2, be2, out);    // 10
}

// round 16
// speedup vs baseline: 1.3470x; 1.1016x over previous
#include <cuda_runtime.h>
#include <cuda_bf16.h>
#include <mma.h>

// Net_12403865551680 — 2-layer GCN + mean-pool + Kronecker BN-MLP head.
// R15: 227.3 (best). 16B gathers gave only -1.5us -> gp NOT load-issue bound.
//      Surviving theory: 50-node block-sync tail (max-of-50 Poisson ~ 1.9x).
// R16: unfuse gp -> gather1 (no block sync, tail ~1.3x; h1 out in bf16)
//      + proj2 (thread-per-node, smem W2, incremental dequant). Rest = R15.

using namespace nvcuda;

typedef unsigned long long ull;

#define NN 100000
#define NE 1600000
#define NG 1024

struct __align__(8) bf4 { __nv_bfloat162 a, b; };
struct __align__(16) bf8 { __nv_bfloat162 a, b, c, d; };

// ---------------- scratch (zero-initialized at module load) ----------------
__device__ __align__(128) bf8   d_hp1b[NN * 13];   // feat@W1, bf16, 104 dims (100 + 4 pad)
__device__ __align__(128) bf8   d_h1b[NN * 13];    // relu(agg+b1), bf16, 104 dims
__device__ __align__(128) float d_hp2[NN * 20];    // h1@W2
__device__ int   d_deg[NN];                        // zeroed by scanC each run
__device__ int   d_bsum[98];
__device__ int   d_rowstart[NN + 1];
__device__ int   d_cursor[NN];
__device__ int   d_csr[NE];
__device__ __align__(128) float d_gsum[NG * 20];   // zeroed by mlp1 each run
__device__ float d_gcnt[NG];                       // zeroed by mlp1 each run
__device__ __align__(128) float d_y1[NG * 128];
__device__ __align__(128) float d_y2[NG * 32];
__device__ float d_s1[2 * 128];   // y1 channel sum | sumsq (zeroed by deg)
__device__ float d_s2[2 * 32];    // y2 channel sum | sumsq (zeroed by deg)

// ---------------- packed f32x2 helpers ----------------
__device__ __forceinline__ ull dup2(float x) {
    ull r; asm("mov.b64 %0, {%1, %1};" : "=l"(r) : "f"(x)); return r;
}
__device__ __forceinline__ ull pk2(float lo, float hi) {
    ull r; asm("mov.b64 %0, {%1, %2};" : "=l"(r) : "f"(lo), "f"(hi)); return r;
}
__device__ __forceinline__ void fma2(ull& d, ull a, ull b) {
    asm("fma.rn.f32x2 %0, %1, %2, %0;" : "+l"(d) : "l"(a), "l"(b));
}
__device__ __forceinline__ float f2lo(ull v) { return __uint_as_float((unsigned)v); }
__device__ __forceinline__ float f2hi(ull v) { return __uint_as_float((unsigned)(v >> 32)); }

// ---------------- degree histogram: 4 edges/thread; zeroes stat partials ----------------
__global__ void deg_kernel(const int* __restrict__ dst) {
    if (blockIdx.x == 0 && threadIdx.x < 256) d_s1[threadIdx.x] = 0.f;
    if (blockIdx.x == 1 && threadIdx.x < 64)  d_s2[threadIdx.x] = 0.f;
    int t = blockIdx.x * blockDim.x + threadIdx.x;
    int e = t * 4;
    if (e + 3 >= NE) {
        for (; e < NE; e++) atomicAdd(&d_deg[dst[e]], 1);
        return;
    }
    int4 d = *(const int4*)(dst + e);
    atomicAdd(&d_deg[d.x], 1);
    atomicAdd(&d_deg[d.y], 1);
    atomicAdd(&d_deg[d.z], 1);
    atomicAdd(&d_deg[d.w], 1);
}

// ---------------- scan phase A: per-block sums (98 x 1024) ----------------
__global__ void __launch_bounds__(1024) sumA_kernel() {
    int b = blockIdx.x;
    int t = threadIdx.x;
    int i = b * 1024 + t;
    int v = (i < NN) ? d_deg[i] : 0;
#pragma unroll
    for (int o = 16; o > 0; o >>= 1) v += __shfl_down_sync(0xffffffffu, v, o);
    __shared__ int ws[32];
    if ((t & 31) == 0) ws[t >> 5] = v;
    __syncthreads();
    if (t < 32) {
        int s = ws[t];
#pragma unroll
        for (int o = 16; o > 0; o >>= 1) s += __shfl_down_sync(0xffffffffu, s, o);
        if (t == 0) d_bsum[b] = s;
    }
}

// ---------------- scan phase C: local scan + own prefix; zeroes d_deg ----------------
__global__ void __launch_bounds__(1024) scanC_kernel() {
    int b = blockIdx.x;
    int t = threadIdx.x;
    int i = b * 1024 + t;
    int v = (i < NN) ? d_deg[i] : 0;
    int lane = t & 31, w = t >> 5;
    int inc = v;
#pragma unroll
    for (int o = 1; o < 32; o <<= 1) {
        int u = __shfl_up_sync(0xffffffffu, inc, o);
        if (lane >= o) inc += u;
    }
    __shared__ int ws[32];
    __shared__ int sboff;
    if (lane == 31) ws[w] = inc;
    __syncthreads();
    if (w == 0) {
        int x = ws[lane];
#pragma unroll
        for (int o = 1; o < 32; o <<= 1) {
            int u = __shfl_up_sync(0xffffffffu, x, o);
            if (lane >= o) x += u;
        }
        ws[lane] = x;
    }
    if (w == 1) {
        int s = 0;
        for (int j = lane; j < b; j += 32) s += d_bsum[j];
#pragma unroll
        for (int o = 16; o > 0; o >>= 1) s += __shfl_down_sync(0xffffffffu, s, o);
        if (lane == 0) sboff = s;
    }
    __syncthreads();
    int excl = inc - v + (w > 0 ? ws[w - 1] : 0) + sboff;
    if (i < NN) {
        d_rowstart[i] = excl;
        d_cursor[i] = excl;
        d_deg[i] = 0;
    }
    if (b == 0 && t == 0) d_rowstart[NN] = NE;
}

// ---------------- CSR fill: 4 edges/thread ----------------
__global__ void fill_kernel(const int* __restrict__ src, const int* __restrict__ dst) {
    int t = blockIdx.x * blockDim.x + threadIdx.x;
    int e = t * 4;
    if (e + 3 >= NE) {
        for (; e < NE; e++) {
            int p = atomicAdd(&d_cursor[dst[e]], 1);
            d_csr[p] = src[e];
        }
        return;
    }
    int4 d = *(const int4*)(dst + e);
    int4 s = *(const int4*)(src + e);
    int p0 = atomicAdd(&d_cursor[d.x], 1);
    int p1 = atomicAdd(&d_cursor[d.y], 1);
    int p2 = atomicAdd(&d_cursor[d.z], 1);
    int p3 = atomicAdd(&d_cursor[d.w], 1);
    d_csr[p0] = s.x;
    d_csr[p1] = s.y;
    d_csr[p2] = s.z;
    d_csr[p3] = s.w;
}

// ---------------- proj1 (tensor cores): hp1(bf16,padded) = feat @ W1 ----------------
__global__ void __launch_bounds__(256) proj1_kernel(const float* __restrict__ X,
                                                    const float* __restrict__ W1) {
    extern __shared__ char smraw[];
    __nv_bfloat16* As = (__nv_bfloat16*)smraw;            // ld 136
    __nv_bfloat16* Bs = (__nv_bfloat16*)(smraw + 34816);  // ld 120
    float* Cs = (float*)smraw;                            // ld 112 (reuse)
    const int tid = threadIdx.x;
    const int w = tid >> 5;
    const int l = tid & 31;
    const int mBase = blockIdx.x * 128;

#pragma unroll
    for (int r = 0; r < 16; r++) {
        int row = w * 16 + r;
        int gn = mBase + row;
        float4 v = (gn < NN) ? *(const float4*)(X + gn * 128 + 4 * l)
                             : make_float4(0.f, 0.f, 0.f, 0.f);
        bf4 o;
        o.a = __floats2bfloat162_rn(v.x, v.y);
        o.b = __floats2bfloat162_rn(v.z, v.w);
        *(bf4*)&As[row * 136 + 4 * l] = o;
    }
#pragma unroll
    for (int r = 0; r < 16; r++) {
        int k = w * 16 + r;
#pragma unroll
        for (int cc = 0; cc < 4; cc++) {
            int n = l + 32 * cc;
            if (n < 112)
                Bs[k * 120 + n] = __float2bfloat16((n < 100) ? W1[k * 100 + n] : 0.f);
        }
    }
    __syncthreads();

    wmma::fragment<wmma::accumulator, 16, 16, 16, float> c[7];
#pragma unroll
    for (int n = 0; n < 7; n++) wmma::fill_fragment(c[n], 0.f);
#pragma unroll
    for (int k = 0; k < 8; k++) {
        wmma::fragment<wmma::matrix_a, 16, 16, 16, __nv_bfloat16, wmma::row_major> a;
        wmma::load_matrix_sync(a, As + (w * 16) * 136 + k * 16, 136);
#pragma unroll
        for (int n = 0; n < 7; n++) {
            wmma::fragment<wmma::matrix_b, 16, 16, 16, __nv_bfloat16, wmma::row_major> b;
            wmma::load_matrix_sync(b, Bs + (k * 16) * 120 + n * 16, 120);
            wmma::mma_sync(c[n], a, b, c[n]);
        }
    }
    __syncthreads();
#pragma unroll
    for (int n = 0; n < 7; n++)
        wmma::store_matrix_sync(Cs + (w * 16) * 112 + n * 16, c[n], 112, wmma::mem_row_major);
    __syncthreads();

    if (l < 26) {
        bf4* outRowBase = (bf4*)d_hp1b;
#pragma unroll
        for (int r = 0; r < 16; r++) {
            int row = w * 16 + r;
            int gn = mBase + row;
            if (gn < NN) {
                bf4 o;
                if (l < 25) {
                    const float* p = Cs + row * 112 + l * 4;
                    o.a = __floats2bfloat162_rn(p[0], p[1]);
                    o.b = __floats2bfloat162_rn(p[2], p[3]);
                } else {
                    o.a = __floats2bfloat162_rn(0.f, 0.f);
                    o.b = __floats2bfloat162_rn(0.f, 0.f);
                }
                outRowBase[gn * 26 + l] = o;
            }
        }
    }
}

// ---------------- gather1: thread-per-(node,chunk), NO block sync ----------------
// h1b[n][c] = bf16( relu( (deg>0 ? mean : self) + b1 ) ), 13 x 8-dim chunks.
__global__ void __launch_bounds__(256) gather1_kernel(const float* __restrict__ b1) {
    int i = blockIdx.x * 256 + threadIdx.x;
    if (i >= NN * 13) return;
    int n = i / 13;
    int c = i - n * 13;
    int row0 = d_rowstart[n];
    int row1 = d_rowstart[n + 1];
    int deg = row1 - row0;

    float a0[8] = {0.f, 0.f, 0.f, 0.f, 0.f, 0.f, 0.f, 0.f};
    float a1[8] = {0.f, 0.f, 0.f, 0.f, 0.f, 0.f, 0.f, 0.f};
    int j = row0;
    for (; j + 1 < row1; j += 2) {
        int s0 = __ldg(&d_csr[j]);
        int s1 = __ldg(&d_csr[j + 1]);
        bf8 v0 = d_hp1b[s0 * 13 + c];
        bf8 v1 = d_hp1b[s1 * 13 + c];
        float2 p0 = __bfloat1622float2(v0.a), p1 = __bfloat1622float2(v0.b);
        float2 p2 = __bfloat1622float2(v0.c), p3 = __bfloat1622float2(v0.d);
        float2 q0 = __bfloat1622float2(v1.a), q1 = __bfloat1622float2(v1.b);
        float2 q2 = __bfloat1622float2(v1.c), q3 = __bfloat1622float2(v1.d);
        a0[0] += p0.x; a0[1] += p0.y; a0[2] += p1.x; a0[3] += p1.y;
        a0[4] += p2.x; a0[5] += p2.y; a0[6] += p3.x; a0[7] += p3.y;
        a1[0] += q0.x; a1[1] += q0.y; a1[2] += q1.x; a1[3] += q1.y;
        a1[4] += q2.x; a1[5] += q2.y; a1[6] += q3.x; a1[7] += q3.y;
    }
    if (j < row1) {
        int s = __ldg(&d_csr[j]);
        bf8 v = d_hp1b[s * 13 + c];
        float2 p0 = __bfloat1622float2(v.a), p1 = __bfloat1622float2(v.b);
        float2 p2 = __bfloat1622float2(v.c), p3 = __bfloat1622float2(v.d);
        a0[0] += p0.x; a0[1] += p0.y; a0[2] += p1.x; a0[3] += p1.y;
        a0[4] += p2.x; a0[5] += p2.y; a0[6] += p3.x; a0[7] += p3.y;
    }
    float r[8];
    if (deg > 0) {
        float inv = 1.f / (float)deg;
#pragma unroll
        for (int q = 0; q < 8; q++) r[q] = (a0[q] + a1[q]) * inv;
    } else {
        bf8 sv = d_hp1b[n * 13 + c];
        float2 p0 = __bfloat1622float2(sv.a), p1 = __bfloat1622float2(sv.b);
        float2 p2 = __bfloat1622float2(sv.c), p3 = __bfloat1622float2(sv.d);
        r[0] = p0.x; r[1] = p0.y; r[2] = p1.x; r[3] = p1.y;
        r[4] = p2.x; r[5] = p2.y; r[6] = p3.x; r[7] = p3.y;
    }
    // bias (zero-padded beyond 100) + relu, emit bf16
    float bb[8];
#pragma unroll
    for (int q = 0; q < 8; q++) {
        int d = c * 8 + q;
        bb[q] = (d < 100) ? __ldg(&b1[d]) : 0.f;
    }
    bf8 o;
    o.a = __floats2bfloat162_rn(fmaxf(r[0] + bb[0], 0.f), fmaxf(r[1] + bb[1], 0.f));
    o.b = __floats2bfloat162_rn(fmaxf(r[2] + bb[2], 0.f), fmaxf(r[3] + bb[3], 0.f));
    o.c = __floats2bfloat162_rn(fmaxf(r[4] + bb[4], 0.f), fmaxf(r[5] + bb[5], 0.f));
    o.d = __floats2bfloat162_rn(fmaxf(r[6] + bb[6], 0.f), fmaxf(r[7] + bb[7], 0.f));
    d_h1b[n * 13 + c] = o;
}

// ---------------- proj2: thread-per-node, hp2 = h1b @ W2, incremental dequant ----------------
__global__ void __launch_bounds__(256) proj2_kernel(const float* __restrict__ W2) {
    __shared__ ull W2d[100 * 10];   // W2d[k*10+p] = (W2[k][2p], W2[k][2p+1])
    int tid = threadIdx.x;
    for (int idx = tid; idx < 1000; idx += 256) {
        float2 wv = *(const float2*)(W2 + 2 * idx);
        W2d[idx] = pk2(wv.x, wv.y);
    }
    __syncthreads();

    int n = blockIdx.x * 256 + tid;
    if (n >= NN) return;

    ull acc[10];
#pragma unroll
    for (int p = 0; p < 10; p++) acc[p] = 0;

#pragma unroll
    for (int c = 0; c < 13; c++) {
        bf8 v = d_h1b[n * 13 + c];
        float2 p0 = __bfloat1622float2(v.a), p1 = __bfloat1622float2(v.b);
        float2 p2 = __bfloat1622float2(v.c), p3 = __bfloat1622float2(v.d);
        float h[8] = {p0.x, p0.y, p1.x, p1.y, p2.x, p2.y, p3.x, p3.y};
#pragma unroll
        for (int q = 0; q < 8; q++) {
            int k = c * 8 + q;
            if (k < 100) {
                ull a = dup2(h[q]);
                const ull* wr = &W2d[k * 10];
#pragma unroll
                for (int p = 0; p < 10; p++) fma2(acc[p], a, wr[p]);
            }
        }
    }
#pragma unroll
    for (int p = 0; p < 10; p++)
        *(float2*)(d_hp2 + n * 20 + 2 * p) = make_float2(f2lo(acc[p]), f2hi(acc[p]));
}

// ---------------- layer-2 gather + fused graph pooling (R15 exact) ----------------
__global__ void __launch_bounds__(256) gather2_kernel(const float* __restrict__ b2,
                                                      const int* __restrict__ n2g) {
    int i = blockIdx.x * 256 + threadIdx.x;
    if (i >= NN * 5) return;
    int n = i / 5;
    int c = i - n * 5;
    int row0 = d_rowstart[n];
    int row1 = d_rowstart[n + 1];
    int deg = row1 - row0;

    float4 a0 = make_float4(0.f, 0.f, 0.f, 0.f);
    float4 a1 = make_float4(0.f, 0.f, 0.f, 0.f);
    float4 a2 = make_float4(0.f, 0.f, 0.f, 0.f);
    float4 a3 = make_float4(0.f, 0.f, 0.f, 0.f);
    int j = row0;
    for (; j + 3 < row1; j += 4) {
        int s0 = __ldg(&d_csr[j]);
        int s1 = __ldg(&d_csr[j + 1]);
        int s2 = __ldg(&d_csr[j + 2]);
        int s3 = __ldg(&d_csr[j + 3]);
        float4 f0 = *(const float4*)(d_hp2 + s0 * 20 + c * 4);
        float4 f1 = *(const float4*)(d_hp2 + s1 * 20 + c * 4);
        float4 f2 = *(const float4*)(d_hp2 + s2 * 20 + c * 4);
        float4 f3 = *(const float4*)(d_hp2 + s3 * 20 + c * 4);
        a0.x += f0.x; a0.y += f0.y; a0.z += f0.z; a0.w += f0.w;
        a1.x += f1.x; a1.y += f1.y; a1.z += f1.z; a1.w += f1.w;
        a2.x += f2.x; a2.y += f2.y; a2.z += f2.z; a2.w += f2.w;
        a3.x += f3.x; a3.y += f3.y; a3.z += f3.z; a3.w += f3.w;
    }
    for (; j < row1; j++) {
        int s = __ldg(&d_csr[j]);
        float4 f = *(const float4*)(d_hp2 + s * 20 + c * 4);
        a0.x += f.x; a0.y += f.y; a0.z += f.z; a0.w += f.w;
    }
    float4 v;
    if (deg > 0) {
        float inv = 1.f / (float)deg;
        v = make_float4((a0.x + a1.x + a2.x + a3.x) * inv,
                        (a0.y + a1.y + a2.y + a3.y) * inv,
                        (a0.z + a1.z + a2.z + a3.z) * inv,
                        (a0.w + a1.w + a2.w + a3.w) * inv);
    } else {
        v = *(const float4*)(d_hp2 + n * 20 + c * 4);
    }
    float4 b = *(const float4*)(b2 + c * 4);
    float4 r = make_float4(fmaxf(v.x + b.x, 0.f), fmaxf(v.y + b.y, 0.f),
                           fmaxf(v.z + b.z, 0.f), fmaxf(v.w + b.w, 0.f));
    int g = n2g[n];
    float* gs = d_gsum + g * 20 + c * 4;
    atomicAdd(gs + 0, r.x);
    atomicAdd(gs + 1, r.y);
    atomicAdd(gs + 2, r.z);
    atomicAdd(gs + 3, r.w);
    if (c == 0) atomicAdd(&d_gcnt[g], 1.f);
}

// ---------------- mlp1: split j-loop + fused y1 channel stats ----------------
__global__ void __launch_bounds__(512) mlp1_kernel(const float* __restrict__ sf,
                                                   const float* __restrict__ Wf1,
                                                   const float* __restrict__ bf1) {
    __shared__ float fs[640 * 8];
    __shared__ float inv[8];
    __shared__ float psum[4][4][256];
    int g0 = blockIdx.x * 8;
    int tid = threadIdx.x;
    if (tid < 8) inv[tid] = 1.f / fmaxf(d_gcnt[g0 + tid], 1.f);
    __syncthreads();
    for (int idx = tid; idx < 640 * 8; idx += 512) {
        int j = idx >> 3;
        int g = idx & 7;
        int k = j >> 5, s = j & 31;
        fs[idx] = d_gsum[(g0 + g) * 20 + k] * inv[g] * sf[(g0 + g) * 32 + s];
    }
    __syncthreads();
    if (tid < 8) d_gcnt[g0 + tid] = 0.f;
    if (tid < 160) d_gsum[g0 * 20 + tid] = 0.f;

    int o = tid & 127;
    int q = tid >> 7;
    ull acc[4] = {0, 0, 0, 0};
    int j0 = q * 160;
#pragma unroll 4
    for (int j = j0; j < j0 + 160; j++) {
        ull wd = dup2(Wf1[j * 128 + o]);
#pragma unroll
        for (int p = 0; p < 4; p++) {
            ull a = *(const ull*)&fs[j * 8 + 2 * p];
            fma2(acc[p], a, wd);
        }
    }
#pragma unroll
    for (int p = 0; p < 4; p++) {
        psum[q][p][2 * o]     = f2lo(acc[p]);
        psum[q][p][2 * o + 1] = f2hi(acc[p]);
    }
    __syncthreads();
    if (tid < 128) {
        float b = bf1[tid];
        float s8 = 0.f, q8 = 0.f;
#pragma unroll
        for (int p = 0; p < 4; p++) {
            float lo = psum[0][p][2 * tid] + psum[1][p][2 * tid]
                     + psum[2][p][2 * tid] + psum[3][p][2 * tid] + b;
            float hi = psum[0][p][2 * tid + 1] + psum[1][p][2 * tid + 1]
                     + psum[2][p][2 * tid + 1] + psum[3][p][2 * tid + 1] + b;
            d_y1[(g0 + 2 * p) * 128 + tid] = lo;
            d_y1[(g0 + 2 * p + 1) * 128 + tid] = hi;
            s8 += lo + hi;
            q8 += lo * lo + hi * hi;
        }
        atomicAdd(&d_s1[tid], s8);
        atomicAdd(&d_s1[128 + tid], q8);
    }
}

// ---------------- mlp2: BN(y1) finalize inline + GEMM + y2 stats ----------------
__global__ void __launch_bounds__(256) mlp2_kernel(const float* __restrict__ Wf2,
                                                   const float* __restrict__ bf2,
                                                   const float* __restrict__ g1,
                                                   const float* __restrict__ be1) {
    __shared__ float gsn[128], bsn[128];
    __shared__ float ssum[32], ssq[32];
    int tid = threadIdx.x;
    if (tid < 128) {
        float s = d_s1[tid], q = d_s1[128 + tid];
        float mu = s * (1.f / (float)NG);
        float var = q * (1.f / (float)NG) - mu * mu;
        float rs = rsqrtf(var + 1e-5f);
        float gm = g1[tid] * rs;
        gsn[tid] = gm;
        bsn[tid] = be1[tid] - mu * gm;
    }
    if (tid < 32) { ssum[tid] = 0.f; ssq[tid] = 0.f; }
    __syncthreads();

    int i = blockIdx.x * 256 + tid;
    int g = i >> 5, o = i & 31;
    float acc = 0.f;
#pragma unroll 4
    for (int k = 0; k < 128; k++) {
        float x = d_y1[g * 128 + k];
        float h = fmaxf(fmaf(x, gsn[k], bsn[k]), 0.f);
        acc = fmaf(h, Wf2[k * 32 + o], acc);
    }
    float val = acc + bf2[o];
    d_y2[g * 32 + o] = val;
    atomicAdd(&ssum[o], val);
    atomicAdd(&ssq[o], val * val);
    __syncthreads();
    if (tid < 32) {
        atomicAdd(&d_s2[tid], ssum[tid]);
        atomicAdd(&d_s2[32 + tid], ssq[tid]);
    }
}

// ---------------- mlp3: BN(y2) finalize inline + final GEMM ----------------
__global__ void __launch_bounds__(256) mlp3_kernel(const float* __restrict__ Wf3,
                                                   const float* __restrict__ bf3,
                                                   const float* __restrict__ g2,
                                                   const float* __restrict__ be2,
                                                   float* __restrict__ out) {
    __shared__ float gsn[32], bsn[32];
    int tid = threadIdx.x;
    if (tid < 32) {
        float s = d_s2[tid], q = d_s2[32 + tid];
        float mu = s * (1.f / (float)NG);
        float var = q * (1.f / (float)NG) - mu * mu;
        float rs = rsqrtf(var + 1e-5f);
        float gm = g2[tid] * rs;
        gsn[tid] = gm;
        bsn[tid] = be2[tid] - mu * gm;
    }
    __syncthreads();

    int i = blockIdx.x * 256 + tid;
    int g = i >> 3, o = i & 7;
    float acc = 0.f;
#pragma unroll
    for (int k = 0; k < 32; k++) {
        float x = d_y2[g * 32 + k];
        float h = fmaxf(fmaf(x, gsn[k], bsn[k]), 0.f);
        acc = fmaf(h, Wf3[k * 8 + o], acc);
    }
    out[i] = acc + bf3[o];
}

extern "C" void kernel_launch(void* const* d_in, const int* in_sizes, int n_in,
                              void* d_out, int out_size) {
    const float* feat = (const float*)d_in[0];
    const float* sf   = (const float*)d_in[1];
    const int*   src  = (const int*)d_in[2];
    const int*   dst  = (const int*)d_in[3];
    const int*   n2g  = (const int*)d_in[4];
    const float* W1   = (const float*)d_in[5];
    const float* b1   = (const float*)d_in[6];
    const float* W2   = (const float*)d_in[7];
    const float* b2   = (const float*)d_in[8];
    const float* Wf1  = (const float*)d_in[9];
    const float* bf1  = (const float*)d_in[10];
    const float* g1   = (const float*)d_in[11];
    const float* be1  = (const float*)d_in[12];
    const float* Wf2  = (const float*)d_in[13];
    const float* bf2  = (const float*)d_in[14];
    const float* g2   = (const float*)d_in[15];
    const float* be2  = (const float*)d_in[16];
    const float* Wf3  = (const float*)d_in[17];
    const float* bf3  = (const float*)d_in[18];
    float* out = (float*)d_out;

    static cudaStream_t s2 = nullptr;
    static cudaEvent_t evFork, evJoin;
    if (!s2) {
        cudaFuncSetAttribute(proj1_kernel,
                             cudaFuncAttributeMaxDynamicSharedMemorySize, 65536);
        cudaStreamCreateWithFlags(&s2, cudaStreamNonBlocking);
        cudaEventCreateWithFlags(&evFork, cudaEventDisableTiming);
        cudaEventCreateWithFlags(&evJoin, cudaEventDisableTiming);
    }

    // fork: CSR-build chain on s2, proj1 on the main stream — independent work
    cudaEventRecord(evFork, 0);
    cudaStreamWaitEvent(s2, evFork, 0);

    deg_kernel<<<(NE / 4 + 255) / 256, 256, 0, s2>>>(dst);         // 1
    sumA_kernel<<<98, 1024, 0, s2>>>();                            // 2
    scanC_kernel<<<98, 1024, 0, s2>>>();                           // 3
    fill_kernel<<<(NE / 4 + 255) / 256, 256, 0, s2>>>(src, dst);   // 4  (ncu slot)
    proj1_kernel<<<782, 256, 65536>>>(feat, W1);                   // 5  (main, concurrent)

    // join
    cudaEventRecord(evJoin, s2);
    cudaStreamWaitEvent(0, evJoin, 0);

    gather1_kernel<<<(NN * 13 + 255) / 256, 256>>>(b1);            // 6  no block sync
    proj2_kernel<<<(NN + 255) / 256, 256>>>(W2);                   // 7
    gather2_kernel<<<(NN * 5 + 255) / 256, 256>>>(b2, n2g);        // 8

    mlp1_kernel<<<NG / 8, 512>>>(sf, Wf1, bf1);                    // 9
    mlp2_kernel<<<NG * 32 / 256, 256>>>(Wf2, bf2, g1, be1);        // 10
    mlp3_kernel<<<NG * 8 / 256, 256>>>(Wf3, bf3, g2, be2, out);    // 11
}